// round 5
// baseline (speedup 1.0000x reference)
#include <cuda_runtime.h>
#include <cstdint>

#define NPTS 4096
#define BATCH 16
#define MCTR 1024
#define KNBR 64
#define FDIM 64
#define H1D  64
#define H2D  64
#define OUTD 128
#define R2C  0.04f
#define CAND_CAP 768

#define FPS_BLOCKS 16
#define FEAT_ROWS 64
#define FEAT_BLOCKS ((BATCH * NPTS) / FEAT_ROWS)   // 1024

#define HPAD 68   // transposed row stride (68*4=272B, 16B aligned)

typedef unsigned long long ull;

// ---------------- device scratch (no allocations allowed) ----------------
__device__ int   g_idx[BATCH * MCTR];
__device__ float g_feat[(size_t)BATCH * NPTS * H1D];   // x @ W1[0:64,:]  (16 MB)

// ---------------- f32x2 packed helpers ----------------
__device__ __forceinline__ ull fma2(ull a, ull b, ull c) {
    ull d;
    asm("fma.rn.f32x2 %0, %1, %2, %3;" : "=l"(d) : "l"(a), "l"(b), "l"(c));
    return d;
}
__device__ __forceinline__ ull pack2(float lo, float hi) {
    ull d;
    asm("mov.b64 %0, {%1, %2};" : "=l"(d) : "f"(lo), "f"(hi));
    return d;
}
__device__ __forceinline__ float2 unpack2(ull v) {
    float2 r;
    asm("mov.b64 {%0, %1}, %2;" : "=f"(r.x), "=f"(r.y) : "l"(v));
    return r;
}

// =========================================================================
// Merged kernel: blocks 0..15 -> FPS (one batch each, 256 thr, 16 pts/thr);
// blocks 16.. -> feat (64 rows each). FPS and feat overlap on the chip.
// =========================================================================
struct alignas(16) MSmem {
    union {
        struct {
            float px[NPTS], py[NPTS], pz[NPTS];          // 48 KB
            ull   part[2][8];
        } fps;
        struct {
            float xx[FEAT_ROWS][65];
            float w[64][64];
        } feat;
    } u;
};

__global__ __launch_bounds__(256) void fpsfeat_kernel(
    const float* __restrict__ pos, float* __restrict__ pos_s_out,
    const float* __restrict__ x,   const float* __restrict__ W1)
{
    extern __shared__ unsigned char smraw[];
    MSmem& sm = *reinterpret_cast<MSmem*>(smraw);
    int tid = threadIdx.x;

    if (blockIdx.x < FPS_BLOCKS) {
        // ------------------------- FPS -------------------------
        auto& S = sm.u.fps;
        int b = blockIdx.x;
        const float* pb = pos + (size_t)b * NPTS * 3;

        float px[16], py[16], pz[16], dst[16];
#pragma unroll
        for (int u = 0; u < 16; u++) {
            int i = tid + u * 256;
            float X = pb[i * 3 + 0], Y = pb[i * 3 + 1], Z = pb[i * 3 + 2];
            S.px[i] = X; S.py[i] = Y; S.pz[i] = Z;
            px[u] = X; py[u] = Y; pz[u] = Z;
            dst[u] = 1e10f;
        }
        __syncthreads();

        int   last = 0;
        float lx = S.px[0], ly = S.py[0], lz = S.pz[0];

        for (int m = 0; m < MCTR; m++) {
            if (tid == 0) {
                g_idx[b * MCTR + m] = last;
                float* po = pos_s_out + ((size_t)(b * MCTR + m)) * 3;
                po[0] = lx; po[1] = ly; po[2] = lz;
            }
            float bv = -1.0f; int bi = 0;
#pragma unroll
            for (int u = 0; u < 16; u++) {
                float dx = px[u] - lx, dy = py[u] - ly, dz = pz[u] - lz;
                float d  = fmaf(dx, dx, fmaf(dy, dy, dz * dz));
                float nd = fminf(dst[u], d);
                dst[u] = nd;
                int gi = tid + u * 256;
                if (nd > bv) { bv = nd; bi = gi; }   // ascending gi -> first occurrence
            }
            ull key = ((ull)__float_as_uint(bv) << 32) | (unsigned)(~(unsigned)bi);
#pragma unroll
            for (int off = 16; off; off >>= 1) {
                ull ok = __shfl_down_sync(0xffffffffu, key, off);
                if (ok > key) key = ok;
            }
            if ((tid & 31) == 0) S.part[m & 1][tid >> 5] = key;
            __syncthreads();
            ull best = S.part[m & 1][0];
#pragma unroll
            for (int w = 1; w < 8; w++) {
                ull k2 = S.part[m & 1][w];
                if (k2 > best) best = k2;
            }
            last = (int)(~(unsigned)best);
            lx = S.px[last]; ly = S.py[last]; lz = S.pz[last];
        }
    } else {
        // ---------------- feat: g = x @ W1[0:64,:]  (f32x2) ----------------
        auto& S = sm.u.feat;
        size_t rbase = (size_t)(blockIdx.x - FPS_BLOCKS) * FEAT_ROWS;

        for (int i = tid; i < 64 * 64; i += 256) S.w[i >> 6][i & 63] = W1[i];
        for (int i = tid; i < FEAT_ROWS * 64; i += 256)
            S.xx[i >> 6][i & 63] = x[rbase * 64 + i];
        __syncthreads();

        int r = tid >> 2, q = tid & 3;
        ull acc[8];
#pragma unroll
        for (int c = 0; c < 8; c++) acc[c] = 0ull;
        for (int k = 0; k < 64; k++) {
            float xv = S.xx[r][k];
            ull xb = pack2(xv, xv);
            const ulonglong2* wp = reinterpret_cast<const ulonglong2*>(&S.w[k][q * 16]);
            ulonglong2 w0 = wp[0], w1 = wp[1], w2 = wp[2], w3 = wp[3];
            acc[0] = fma2(xb, w0.x, acc[0]); acc[1] = fma2(xb, w0.y, acc[1]);
            acc[2] = fma2(xb, w1.x, acc[2]); acc[3] = fma2(xb, w1.y, acc[3]);
            acc[4] = fma2(xb, w2.x, acc[4]); acc[5] = fma2(xb, w2.y, acc[5]);
            acc[6] = fma2(xb, w3.x, acc[6]); acc[7] = fma2(xb, w3.y, acc[7]);
        }
        float* go = g_feat + (rbase + r) * 64 + q * 16;
#pragma unroll
        for (int c = 0; c < 4; c++) {
            float2 a = unpack2(acc[c * 2]), bq = unpack2(acc[c * 2 + 1]);
            *reinterpret_cast<float4*>(go + c * 4) = make_float4(a.x, a.y, bq.x, bq.y);
        }
    }
}

// =========================================================================
// Per-center kernel (256 threads, 2 blocks/SM): rank-count selection +
// f32x2 MLP with TRANSPOSED activations (h[k][neighbor]) + max pool.
// =========================================================================
struct alignas(16) CKSmem {
    union {
        ull   keys[CAND_CAP];     // 6 KB (selection)
        float W2s[64 * 64];       // 16 KB (MLP)
    } u;
    float W3s[64 * 128];          // 32 KB
    float h1t[64][HPAD];          // [k][nbr], 17.4 KB
    float h2t[64][HPAD];
    float red[8][128];            // 4 KB
    float W1bs[3][64];
    float b1s[64], b2s[64], b3s[128];
    float rel[KNBR][3];
    int   nbr[KNBR];
    float ctr[3];
    int   cnt;
    int   nvalid;
};

__global__ __launch_bounds__(256, 2) void center_kernel(
    const float* __restrict__ pos,
    const float* __restrict__ W1, const float* __restrict__ b1,
    const float* __restrict__ W2, const float* __restrict__ b2,
    const float* __restrict__ W3, const float* __restrict__ b3,
    float* __restrict__ out)
{
    extern __shared__ unsigned char smraw[];
    CKSmem& s = *reinterpret_cast<CKSmem*>(smraw);

    int tid = threadIdx.x;
    int blk = blockIdx.x;
    int b = blk >> 10;
    const float* pb = pos + (size_t)b * NPTS * 3;

    if (tid == 0) {
        int ci = g_idx[blk];
        s.ctr[0] = pb[ci * 3 + 0];
        s.ctr[1] = pb[ci * 3 + 1];
        s.ctr[2] = pb[ci * 3 + 2];
        s.cnt = 0;
    }
    if (tid < KNBR) {
        s.nbr[tid] = 0;
        s.rel[tid][0] = 0.f; s.rel[tid][1] = 0.f; s.rel[tid][2] = 0.f;
    }
    __syncthreads();
    float cx = s.ctr[0], cy = s.ctr[1], cz = s.ctr[2];

    // ---- phase 1: candidates within R^2, key = d2_bits<<32 | idx ----
    for (int i = tid; i < NPTS; i += 256) {
        float dx = pb[i * 3 + 0] - cx;
        float dy = pb[i * 3 + 1] - cy;
        float dz = pb[i * 3 + 2] - cz;
        float d2 = fmaf(dx, dx, fmaf(dy, dy, dz * dz));
        if (d2 <= R2C) {
            int p = atomicAdd(&s.cnt, 1);
            if (p < CAND_CAP)
                s.u.keys[p] = ((ull)__float_as_uint(d2) << 32) | (unsigned)i;
        }
    }
    __syncthreads();
    int n  = min(s.cnt, CAND_CAP);
    int nv = min(n, KNBR);

    // ---- phase 2: rank-count selection (exact top-K set by (d2, idx)) ----
    {
        ull myk[3]; int rnk[3];
#pragma unroll
        for (int t = 0; t < 3; t++) {
            int i = tid + t * 256;
            myk[t] = (i < n) ? s.u.keys[i] : ~0ull;
            rnk[t] = 0;
        }
        for (int j = 0; j < n; j++) {
            ull kj = s.u.keys[j];
#pragma unroll
            for (int t = 0; t < 3; t++) rnk[t] += (kj < myk[t]) ? 1 : 0;
        }
#pragma unroll
        for (int t = 0; t < 3; t++) {
            int i = tid + t * 256;
            if (i < n && rnk[t] < KNBR) {
                int idx = (int)(myk[t] & 0xffffffffu);
                s.nbr[rnk[t]] = idx;
                s.rel[rnk[t]][0] = pb[idx * 3 + 0] - cx;
                s.rel[rnk[t]][1] = pb[idx * 3 + 1] - cy;
                s.rel[rnk[t]][2] = pb[idx * 3 + 2] - cz;
            }
        }
        if (tid == 0) s.nvalid = nv;
    }
    __syncthreads();   // keys dead; union becomes W2s

    // ---- load weights to smem ----
    for (int i = tid; i < 64 * 64; i += 256)  s.u.W2s[i] = W2[i];
    for (int i = tid; i < 64 * 128; i += 256) s.W3s[i]   = W3[i];
    for (int i = tid; i < 3 * 64; i += 256)   s.W1bs[i >> 6][i & 63] = W1[64 * 64 + i];
    if (tid < 64)       { s.b1s[tid] = b1[tid]; s.b2s[tid] = b2[tid]; }
    else if (tid < 192) s.b3s[tid - 64] = b3[tid - 64];
    __syncthreads();

    int nvalid = s.nvalid;

    // ---- h1: thread = (neighbor nl=tid/4, 16 channels); store TRANSPOSED ----
    {
        int nl = tid >> 2, q = tid & 3;
        int j = s.nbr[nl];
        const float4* gr = reinterpret_cast<const float4*>(
            g_feat + ((size_t)(b * NPTS + j)) * 64 + q * 16);
        float rx = s.rel[nl][0], ry = s.rel[nl][1], rz = s.rel[nl][2];
#pragma unroll
        for (int c4 = 0; c4 < 4; c4++) {
            float4 g = gr[c4];
            float v[4] = {g.x, g.y, g.z, g.w};
#pragma unroll
            for (int c = 0; c < 4; c++) {
                int ch = q * 16 + c4 * 4 + c;
                float t = v[c];
                t = fmaf(rx, s.W1bs[0][ch], t);
                t = fmaf(ry, s.W1bs[1][ch], t);
                t = fmaf(rz, s.W1bs[2][ch], t);
                t += s.b1s[ch];
                s.h1t[ch][nl] = fmaxf(t, 0.f);   // transposed scatter (one-time)
            }
        }
    }
    __syncthreads();

    // ---- h2: thread = (4ch c4g, 4nbr ng); neighbor-packed f32x2 ----
    {
        int c4g = tid & 15, ng = tid >> 4;
        int n0 = ng * 4;
        ull acc[4][2];
#pragma unroll
        for (int c = 0; c < 4; c++) { acc[c][0] = 0ull; acc[c][1] = 0ull; }
        for (int k = 0; k < 64; k++) {
            ulonglong2 hp = *reinterpret_cast<const ulonglong2*>(&s.h1t[k][n0]);
            float4 w = *reinterpret_cast<const float4*>(&s.u.W2s[k * 64 + c4g * 4]);
            ull wd0 = pack2(w.x, w.x), wd1 = pack2(w.y, w.y);
            ull wd2 = pack2(w.z, w.z), wd3 = pack2(w.w, w.w);
            acc[0][0] = fma2(hp.x, wd0, acc[0][0]); acc[0][1] = fma2(hp.y, wd0, acc[0][1]);
            acc[1][0] = fma2(hp.x, wd1, acc[1][0]); acc[1][1] = fma2(hp.y, wd1, acc[1][1]);
            acc[2][0] = fma2(hp.x, wd2, acc[2][0]); acc[2][1] = fma2(hp.y, wd2, acc[2][1]);
            acc[3][0] = fma2(hp.x, wd3, acc[3][0]); acc[3][1] = fma2(hp.y, wd3, acc[3][1]);
        }
#pragma unroll
        for (int c = 0; c < 4; c++) {
            int ch = c4g * 4 + c;
            float bb = s.b2s[ch];
            float2 p0 = unpack2(acc[c][0]), p1 = unpack2(acc[c][1]);
            *reinterpret_cast<float4*>(&s.h2t[ch][n0]) =
                make_float4(fmaxf(p0.x + bb, 0.f), fmaxf(p0.y + bb, 0.f),
                            fmaxf(p1.x + bb, 0.f), fmaxf(p1.y + bb, 0.f));
        }
    }
    __syncthreads();

    // ---- h3 + max: thread = (4ch of 128 c4g, 8nbr ng); neighbor-packed ----
    {
        int c4g = tid & 31, ng = tid >> 5;
        int n0 = ng * 8;
        ull acc[4][4];
#pragma unroll
        for (int c = 0; c < 4; c++)
#pragma unroll
            for (int p = 0; p < 4; p++) acc[c][p] = 0ull;

        for (int k = 0; k < 64; k++) {
            ulonglong2 hA = *reinterpret_cast<const ulonglong2*>(&s.h2t[k][n0]);
            ulonglong2 hB = *reinterpret_cast<const ulonglong2*>(&s.h2t[k][n0 + 4]);
            float4 w = *reinterpret_cast<const float4*>(&s.W3s[k * 128 + c4g * 4]);
            ull wd[4] = {pack2(w.x, w.x), pack2(w.y, w.y),
                         pack2(w.z, w.z), pack2(w.w, w.w)};
#pragma unroll
            for (int c = 0; c < 4; c++) {
                acc[c][0] = fma2(hA.x, wd[c], acc[c][0]);
                acc[c][1] = fma2(hA.y, wd[c], acc[c][1]);
                acc[c][2] = fma2(hB.x, wd[c], acc[c][2]);
                acc[c][3] = fma2(hB.y, wd[c], acc[c][3]);
            }
        }
        // masked max over this thread's 8 neighbors
        int lim = nvalid - n0;           // #valid in [n0, n0+8)
        float mx[4];
#pragma unroll
        for (int c = 0; c < 4; c++) {
            float m = -1e30f;
#pragma unroll
            for (int p = 0; p < 4; p++) {
                float2 v = unpack2(acc[c][p]);
                if (2 * p + 0 < lim) m = fmaxf(m, v.x);
                if (2 * p + 1 < lim) m = fmaxf(m, v.y);
            }
            mx[c] = m;
        }
        *reinterpret_cast<float4*>(&s.red[ng][c4g * 4]) =
            make_float4(mx[0], mx[1], mx[2], mx[3]);
    }
    __syncthreads();

    if (tid < 128) {
        float v = s.red[0][tid];
#pragma unroll
        for (int w = 1; w < 8; w++) v = fmaxf(v, s.red[w][tid]);
        out[(size_t)blk * OUTD + tid] = v + s.b3s[tid];
    }
}

// =========================================================================
extern "C" void kernel_launch(void* const* d_in, const int* in_sizes, int n_in,
                              void* d_out, int out_size)
{
    const float* x   = (const float*)d_in[0];
    const float* pos = (const float*)d_in[1];
    const float* W1  = (const float*)d_in[2];
    const float* b1  = (const float*)d_in[3];
    const float* W2  = (const float*)d_in[4];
    const float* b2  = (const float*)d_in[5];
    const float* W3  = (const float*)d_in[6];
    const float* b3  = (const float*)d_in[7];

    float* out       = (float*)d_out;                          // [B, M, OUT]
    float* pos_s_out = out + (size_t)BATCH * MCTR * OUTD;      // [B, M, 3]

    cudaFuncSetAttribute(fpsfeat_kernel,
                         cudaFuncAttributeMaxDynamicSharedMemorySize,
                         (int)sizeof(MSmem));
    cudaFuncSetAttribute(center_kernel,
                         cudaFuncAttributeMaxDynamicSharedMemorySize,
                         (int)sizeof(CKSmem));

    fpsfeat_kernel<<<FPS_BLOCKS + FEAT_BLOCKS, 256, sizeof(MSmem)>>>(
        pos, pos_s_out, x, W1);
    center_kernel<<<BATCH * MCTR, 256, sizeof(CKSmem)>>>(
        pos, W1, b1, W2, b2, W3, b3, out);
}

// round 7
// speedup vs baseline: 1.3102x; 1.3102x over previous
#include <cuda_runtime.h>
#include <cuda_bf16.h>
#include <cstdint>

#define NPTS 4096
#define BATCH 16
#define MCTR 1024
#define KNBR 64
#define OUTD 128
#define R2C  0.04f
#define CANDC 512

#define FPS_BLOCKS 16
#define FEAT_ROWS 64
#define FEAT_BLOCKS ((BATCH * NPTS) / FEAT_ROWS)   // 1024

#define AST 36   // padded u32 stride for bf16-pair tiles (conflict-free frags)

typedef unsigned long long ull;
typedef unsigned int u32;
typedef unsigned short u16;

// ---------------- device scratch ----------------
__device__ int   g_idx[BATCH * MCTR];
__device__ float g_feat[(size_t)BATCH * NPTS * 64];   // x @ W1[0:64,:]

// ---------------- f32x2 helpers (feat kernel) ----------------
__device__ __forceinline__ ull fma2(ull a, ull b, ull c) {
    ull d; asm("fma.rn.f32x2 %0, %1, %2, %3;" : "=l"(d) : "l"(a), "l"(b), "l"(c));
    return d;
}
__device__ __forceinline__ ull pack2(float lo, float hi) {
    ull d; asm("mov.b64 %0, {%1, %2};" : "=l"(d) : "f"(lo), "f"(hi)); return d;
}
__device__ __forceinline__ float2 unpack2(ull v) {
    float2 r; asm("mov.b64 {%0, %1}, %2;" : "=f"(r.x), "=f"(r.y) : "l"(v)); return r;
}

// ---------------- mma.sync m16n8k16 bf16 ----------------
__device__ __forceinline__ void mma16816(float* c, u32 a0, u32 a1, u32 a2, u32 a3,
                                         u32 b0, u32 b1) {
    asm volatile(
        "mma.sync.aligned.m16n8k16.row.col.f32.bf16.bf16.f32 "
        "{%0,%1,%2,%3}, {%4,%5,%6,%7}, {%8,%9}, {%0,%1,%2,%3};"
        : "+f"(c[0]), "+f"(c[1]), "+f"(c[2]), "+f"(c[3])
        : "r"(a0), "r"(a1), "r"(a2), "r"(a3), "r"(b0), "r"(b1));
}

// split fp32 -> bf16 hi + bf16 lo (residual)
__device__ __forceinline__ void split_bf16(float v, u16& hi, u16& lo) {
    __nv_bfloat16 bh = __float2bfloat16(v);
    float r = v - __bfloat162float(bh);
    __nv_bfloat16 bl = __float2bfloat16(r);
    hi = __bfloat16_as_ushort(bh);
    lo = __bfloat16_as_ushort(bl);
}
__device__ __forceinline__ u32 split_pack_hi(float v0, float v1) {
    u16 h0, l0, h1, l1;
    split_bf16(v0, h0, l0); split_bf16(v1, h1, l1);
    return (u32)h0 | ((u32)h1 << 16);
}
__device__ __forceinline__ u32 split_pack_lo(float v0, float v1) {
    u16 h0, l0, h1, l1;
    split_bf16(v0, h0, l0); split_bf16(v1, h1, l1);
    return (u32)l0 | ((u32)l1 << 16);
}

// =========================================================================
// fpsfeat: blocks 0..15 FPS (redux.sync argmax), blocks 16.. feat GEMM
// =========================================================================
struct alignas(16) MSmem {
    union {
        struct {
            float px[NPTS], py[NPTS], pz[NPTS];
            ull   part[2][8];
        } fps;
        struct {
            float xx[FEAT_ROWS][65];
            float w[64][64];
        } feat;
    } u;
};

__global__ __launch_bounds__(256) void fpsfeat_kernel(
    const float* __restrict__ pos, float* __restrict__ pos_s_out,
    const float* __restrict__ x,   const float* __restrict__ W1)
{
    extern __shared__ unsigned char smraw[];
    MSmem& sm = *reinterpret_cast<MSmem*>(smraw);
    int tid = threadIdx.x;

    if (blockIdx.x < FPS_BLOCKS) {
        auto& S = sm.u.fps;
        int b = blockIdx.x;
        const float* pb = pos + (size_t)b * NPTS * 3;

        float px[16], py[16], pz[16], dst[16];
#pragma unroll
        for (int u = 0; u < 16; u++) {
            int i = tid + u * 256;
            float X = pb[i * 3 + 0], Y = pb[i * 3 + 1], Z = pb[i * 3 + 2];
            S.px[i] = X; S.py[i] = Y; S.pz[i] = Z;
            px[u] = X; py[u] = Y; pz[u] = Z;
            dst[u] = 1e10f;
        }
        __syncthreads();

        int   last = 0;
        float lx = S.px[0], ly = S.py[0], lz = S.pz[0];

        for (int m = 0; m < MCTR; m++) {
            if (tid == 0) {
                g_idx[b * MCTR + m] = last;
                float* po = pos_s_out + ((size_t)(b * MCTR + m)) * 3;
                po[0] = lx; po[1] = ly; po[2] = lz;
            }
            float bv = -1.0f; int bi = 0;
#pragma unroll
            for (int u = 0; u < 16; u++) {
                float dx = px[u] - lx, dy = py[u] - ly, dz = pz[u] - lz;
                float d  = fmaf(dx, dx, fmaf(dy, dy, dz * dz));
                float nd = fminf(dst[u], d);
                dst[u] = nd;
                int gi = tid + u * 256;
                if (nd > bv) { bv = nd; bi = gi; }
            }
            unsigned bvb  = __float_as_uint(bv);
            unsigned wmax = __reduce_max_sync(0xffffffffu, bvb);
            unsigned cand = (bvb == wmax) ? (unsigned)bi : 0xffffffffu;
            unsigned wbi  = __reduce_min_sync(0xffffffffu, cand);
            ull key = ((ull)wmax << 32) | (unsigned)(~wbi);
            if ((tid & 31) == 0) S.part[m & 1][tid >> 5] = key;
            __syncthreads();
            ull best = S.part[m & 1][0];
#pragma unroll
            for (int w = 1; w < 8; w++) {
                ull k2 = S.part[m & 1][w];
                if (k2 > best) best = k2;
            }
            last = (int)(~(unsigned)best);
            lx = S.px[last]; ly = S.py[last]; lz = S.pz[last];
        }
    } else {
        auto& S = sm.u.feat;
        size_t rbase = (size_t)(blockIdx.x - FPS_BLOCKS) * FEAT_ROWS;

        for (int i = tid; i < 64 * 64; i += 256) S.w[i >> 6][i & 63] = W1[i];
        for (int i = tid; i < FEAT_ROWS * 64; i += 256)
            S.xx[i >> 6][i & 63] = x[rbase * 64 + i];
        __syncthreads();

        int r = tid >> 2, q = tid & 3;
        ull acc[8];
#pragma unroll
        for (int c = 0; c < 8; c++) acc[c] = 0ull;
        for (int k = 0; k < 64; k++) {
            float xv = S.xx[r][k];
            ull xb = pack2(xv, xv);
            const ulonglong2* wp = reinterpret_cast<const ulonglong2*>(&S.w[k][q * 16]);
            ulonglong2 w0 = wp[0], w1 = wp[1], w2 = wp[2], w3 = wp[3];
            acc[0] = fma2(xb, w0.x, acc[0]); acc[1] = fma2(xb, w0.y, acc[1]);
            acc[2] = fma2(xb, w1.x, acc[2]); acc[3] = fma2(xb, w1.y, acc[3]);
            acc[4] = fma2(xb, w2.x, acc[4]); acc[5] = fma2(xb, w2.y, acc[5]);
            acc[6] = fma2(xb, w3.x, acc[6]); acc[7] = fma2(xb, w3.y, acc[7]);
        }
        float* go = g_feat + (rbase + r) * 64 + q * 16;
#pragma unroll
        for (int c = 0; c < 4; c++) {
            float2 a = unpack2(acc[c * 2]), bq = unpack2(acc[c * 2 + 1]);
            *reinterpret_cast<float4*>(go + c * 4) = make_float4(a.x, a.y, bq.x, bq.y);
        }
    }
}

// =========================================================================
// center kernel: 2 centers/block (128 A-rows), 256 threads = 8 warps.
// Each warp owns 16 A-rows; layers 2-3 are barrier-free mma.sync chains.
// =========================================================================
struct alignas(16) CKS {
    ull   keys[2 * CANDC];        // 8 KB
    u32   Ah[128 * AST];          // 18.4 KB  bf16-pair A tile (hi)
    u32   Al[128 * AST];          //           (lo)
    u32   W2h[64 * AST];          // 9.2 KB   W2^T [n][k]
    u32   W2l[64 * AST];
    u32   W3h[128 * AST];         // 18.4 KB  W3^T [n][k]
    u32   W3l[128 * AST];
    float pool[8][132];
    float b1s[64], b2s[64], b3s[128];
    float w1b[3 * 64];
    float rel[128 * 3];
    int   nbr[128];
    float ctr[6];
    int   cnt[2], nvv[2];
};

__global__ __launch_bounds__(256, 2) void center_kernel(
    const float* __restrict__ pos,
    const float* __restrict__ W1, const float* __restrict__ b1,
    const float* __restrict__ W2, const float* __restrict__ b2,
    const float* __restrict__ W3, const float* __restrict__ b3,
    float* __restrict__ out)
{
    extern __shared__ unsigned char smraw[];
    CKS& s = *reinterpret_cast<CKS*>(smraw);

    int tid = threadIdx.x;
    int wid = tid >> 5, lane = tid & 31;
    int blk = blockIdx.x;
    int c0  = blk * 2;
    int b   = c0 >> 10;
    const float* pb = pos + (size_t)b * NPTS * 3;

    if (tid == 0) {
        s.cnt[0] = 0; s.cnt[1] = 0;
        int ci0 = g_idx[c0], ci1 = g_idx[c0 + 1];
        s.ctr[0] = pb[ci0 * 3 + 0]; s.ctr[1] = pb[ci0 * 3 + 1]; s.ctr[2] = pb[ci0 * 3 + 2];
        s.ctr[3] = pb[ci1 * 3 + 0]; s.ctr[4] = pb[ci1 * 3 + 1]; s.ctr[5] = pb[ci1 * 3 + 2];
    }
    if (tid < 128) {
        s.nbr[tid] = 0;
        s.rel[tid * 3 + 0] = 0.f; s.rel[tid * 3 + 1] = 0.f; s.rel[tid * 3 + 2] = 0.f;
    }
    __syncthreads();
    float cx0 = s.ctr[0], cy0 = s.ctr[1], cz0 = s.ctr[2];
    float cx1 = s.ctr[3], cy1 = s.ctr[4], cz1 = s.ctr[5];

    // ---- phase 1: shared candidate scan for both centers ----
    for (int i = tid; i < NPTS; i += 256) {
        float X = pb[i * 3 + 0], Y = pb[i * 3 + 1], Z = pb[i * 3 + 2];
        float dx0 = X - cx0, dy0 = Y - cy0, dz0 = Z - cz0;
        float d20 = fmaf(dx0, dx0, fmaf(dy0, dy0, dz0 * dz0));
        if (d20 <= R2C) {
            int p = atomicAdd(&s.cnt[0], 1);
            if (p < CANDC) s.keys[p] = ((ull)__float_as_uint(d20) << 32) | (unsigned)i;
        }
        float dx1 = X - cx1, dy1 = Y - cy1, dz1 = Z - cz1;
        float d21 = fmaf(dx1, dx1, fmaf(dy1, dy1, dz1 * dz1));
        if (d21 <= R2C) {
            int p = atomicAdd(&s.cnt[1], 1);
            if (p < CANDC) s.keys[CANDC + p] = ((ull)__float_as_uint(d21) << 32) | (unsigned)i;
        }
    }
    __syncthreads();

    // ---- phase 2: rank-count selection per center ----
    for (int cc = 0; cc < 2; cc++) {
        int n  = min(s.cnt[cc], CANDC);
        int nv = min(n, KNBR);
        const ull* kk = s.keys + cc * CANDC;
        float ccx = cc ? cx1 : cx0, ccy = cc ? cy1 : cy0, ccz = cc ? cz1 : cz0;
        ull myk[2]; int rnk[2];
#pragma unroll
        for (int t = 0; t < 2; t++) {
            int i = tid + t * 256;
            myk[t] = (i < n) ? kk[i] : ~0ull;
            rnk[t] = 0;
        }
        for (int j = 0; j < n; j++) {
            ull kj = kk[j];
#pragma unroll
            for (int t = 0; t < 2; t++) rnk[t] += (kj < myk[t]) ? 1 : 0;
        }
#pragma unroll
        for (int t = 0; t < 2; t++) {
            int i = tid + t * 256;
            if (i < n && rnk[t] < KNBR) {
                int idx = (int)(myk[t] & 0xffffffffu);
                int slot = cc * 64 + rnk[t];
                s.nbr[slot] = idx;
                s.rel[slot * 3 + 0] = pb[idx * 3 + 0] - ccx;
                s.rel[slot * 3 + 1] = pb[idx * 3 + 1] - ccy;
                s.rel[slot * 3 + 2] = pb[idx * 3 + 2] - ccz;
            }
        }
        if (tid == 0) s.nvv[cc] = nv;
    }

    // ---- weights: load, split to bf16 hi/lo, store [n][k] packed ----
    for (int i = tid; i < 64 * 64; i += 256) {        // W2: n=i>>6, k=i&63
        int nn = i >> 6, k = i & 63;
        u16 hi, lo;
        split_bf16(W2[k * 64 + nn], hi, lo);
        int w = nn * AST + (k >> 1);
        ((u16*)&s.W2h[w])[k & 1] = hi;
        ((u16*)&s.W2l[w])[k & 1] = lo;
    }
    for (int i = tid; i < 128 * 64; i += 256) {       // W3: n=i>>6, k=i&63
        int nn = i >> 6, k = i & 63;
        u16 hi, lo;
        split_bf16(W3[k * 128 + nn], hi, lo);
        int w = nn * AST + (k >> 1);
        ((u16*)&s.W3h[w])[k & 1] = hi;
        ((u16*)&s.W3l[w])[k & 1] = lo;
    }
    if (tid < 192) s.w1b[tid] = W1[64 * 64 + tid];
    if (tid < 64)       { s.b1s[tid] = b1[tid]; s.b2s[tid] = b2[tid]; }
    else if (tid < 192) s.b3s[tid - 64] = b3[tid - 64];
    __syncthreads();

    int nv0 = s.nvv[0], nv1 = s.nvv[1];

    // ---- h1 (scalar fp32) -> split bf16 A tile; thread = (row, 32 ch) ----
    {
        int row = tid >> 1, half = tid & 1;
        int j = s.nbr[row];
        const float4* gr = reinterpret_cast<const float4*>(
            g_feat + ((size_t)(b * NPTS + j)) * 64 + half * 32);
        float rx = s.rel[row * 3 + 0], ry = s.rel[row * 3 + 1], rz = s.rel[row * 3 + 2];
#pragma unroll
        for (int c4 = 0; c4 < 8; c4++) {
            float4 g = gr[c4];
            float v[4] = {g.x, g.y, g.z, g.w};
            float o[4];
#pragma unroll
            for (int c = 0; c < 4; c++) {
                int ch = half * 32 + c4 * 4 + c;
                float t = v[c];
                t = fmaf(rx, s.w1b[ch], t);
                t = fmaf(ry, s.w1b[64 + ch], t);
                t = fmaf(rz, s.w1b[128 + ch], t);
                o[c] = fmaxf(t + s.b1s[ch], 0.f);
            }
            int w = row * AST + half * 16 + c4 * 2;
            s.Ah[w]     = split_pack_hi(o[0], o[1]);
            s.Al[w]     = split_pack_lo(o[0], o[1]);
            s.Ah[w + 1] = split_pack_hi(o[2], o[3]);
            s.Al[w + 1] = split_pack_lo(o[2], o[3]);
        }
    }
    __syncthreads();

    int r0 = wid * 16 + (lane >> 2);   // this thread's low A-row
    int lp = lane & 3;

    // ================= layer 2: h2[128,64] = A @ W2^T =================
    {
        float acc[8][4];
#pragma unroll
        for (int nt = 0; nt < 8; nt++)
#pragma unroll
            for (int c = 0; c < 4; c++) acc[nt][c] = 0.f;

#pragma unroll
        for (int kt = 0; kt < 4; kt++) {
            int aw = kt * 8 + lp;
            u32 ah0 = s.Ah[r0 * AST + aw],       ah1 = s.Ah[(r0 + 8) * AST + aw];
            u32 ah2 = s.Ah[r0 * AST + aw + 4],   ah3 = s.Ah[(r0 + 8) * AST + aw + 4];
            u32 al0 = s.Al[r0 * AST + aw],       al1 = s.Al[(r0 + 8) * AST + aw];
            u32 al2 = s.Al[r0 * AST + aw + 4],   al3 = s.Al[(r0 + 8) * AST + aw + 4];
#pragma unroll
            for (int nt = 0; nt < 8; nt++) {
                int n = nt * 8 + (lane >> 2);
                u32 bh0 = s.W2h[n * AST + aw], bh1 = s.W2h[n * AST + aw + 4];
                u32 bl0 = s.W2l[n * AST + aw], bl1 = s.W2l[n * AST + aw + 4];
                mma16816(acc[nt], ah0, ah1, ah2, ah3, bh0, bh1);
                mma16816(acc[nt], ah0, ah1, ah2, ah3, bl0, bl1);
                mma16816(acc[nt], al0, al1, al2, al3, bh0, bh1);
            }
        }
        // epilogue: bias + relu + split back into A tile (own rows only)
#pragma unroll
        for (int nt = 0; nt < 8; nt++) {
            int cn = nt * 8 + lp * 2;
            float bb0 = s.b2s[cn], bb1 = s.b2s[cn + 1];
            float v0 = fmaxf(acc[nt][0] + bb0, 0.f);
            float v1 = fmaxf(acc[nt][1] + bb1, 0.f);
            float v2 = fmaxf(acc[nt][2] + bb0, 0.f);
            float v3 = fmaxf(acc[nt][3] + bb1, 0.f);
            int w = nt * 4 + lp;
            s.Ah[r0 * AST + w]       = split_pack_hi(v0, v1);
            s.Al[r0 * AST + w]       = split_pack_lo(v0, v1);
            s.Ah[(r0 + 8) * AST + w] = split_pack_hi(v2, v3);
            s.Al[(r0 + 8) * AST + w] = split_pack_lo(v2, v3);
        }
    }
    __syncwarp();   // warp-local A rows: writes visible to own warp's loads

    // ================= layer 3: out[128,128] = A @ W3^T + masked max ====
    {
        int rin = (wid & 3) * 16 + (lane >> 2);   // row within center block
        int nv  = (wid >> 2) ? nv1 : nv0;
        bool va = rin < nv, vb = (rin + 8) < nv;

        for (int hhalf = 0; hhalf < 2; hhalf++) {
            float acc[8][4];
#pragma unroll
            for (int nt = 0; nt < 8; nt++)
#pragma unroll
                for (int c = 0; c < 4; c++) acc[nt][c] = 0.f;

#pragma unroll
            for (int kt = 0; kt < 4; kt++) {
                int aw = kt * 8 + lp;
                u32 ah0 = s.Ah[r0 * AST + aw],     ah1 = s.Ah[(r0 + 8) * AST + aw];
                u32 ah2 = s.Ah[r0 * AST + aw + 4], ah3 = s.Ah[(r0 + 8) * AST + aw + 4];
                u32 al0 = s.Al[r0 * AST + aw],     al1 = s.Al[(r0 + 8) * AST + aw];
                u32 al2 = s.Al[r0 * AST + aw + 4], al3 = s.Al[(r0 + 8) * AST + aw + 4];
#pragma unroll
                for (int nt = 0; nt < 8; nt++) {
                    int n = hhalf * 64 + nt * 8 + (lane >> 2);
                    u32 bh0 = s.W3h[n * AST + aw], bh1 = s.W3h[n * AST + aw + 4];
                    u32 bl0 = s.W3l[n * AST + aw], bl1 = s.W3l[n * AST + aw + 4];
                    mma16816(acc[nt], ah0, ah1, ah2, ah3, bh0, bh1);
                    mma16816(acc[nt], ah0, ah1, ah2, ah3, bl0, bl1);
                    mma16816(acc[nt], al0, al1, al2, al3, bh0, bh1);
                }
            }
            // masked max across this thread's 2 rows, then across the warp
#pragma unroll
            for (int nt = 0; nt < 8; nt++) {
                float m0 = fmaxf(va ? acc[nt][0] : -1e30f, vb ? acc[nt][2] : -1e30f);
                float m1 = fmaxf(va ? acc[nt][1] : -1e30f, vb ? acc[nt][3] : -1e30f);
#pragma unroll
                for (int off = 16; off >= 4; off >>= 1) {
                    m0 = fmaxf(m0, __shfl_down_sync(0xffffffffu, m0, off));
                    m1 = fmaxf(m1, __shfl_down_sync(0xffffffffu, m1, off));
                }
                if (lane < 4) {
                    int cn = hhalf * 64 + nt * 8 + lane * 2;
                    s.pool[wid][cn]     = m0;
                    s.pool[wid][cn + 1] = m1;
                }
            }
        }
    }
    __syncthreads();

    // ---- combine 4 warps per center + bias ----
    {
        int center = tid >> 7, ch = tid & 127;
        int w0 = center * 4;
        float v = s.pool[w0][ch];
        v = fmaxf(v, s.pool[w0 + 1][ch]);
        v = fmaxf(v, s.pool[w0 + 2][ch]);
        v = fmaxf(v, s.pool[w0 + 3][ch]);
        out[(size_t)(c0 + center) * OUTD + ch] = v + s.b3s[ch];
    }
}

// =========================================================================
extern "C" void kernel_launch(void* const* d_in, const int* in_sizes, int n_in,
                              void* d_out, int out_size)
{
    const float* x   = (const float*)d_in[0];
    const float* pos = (const float*)d_in[1];
    const float* W1  = (const float*)d_in[2];
    const float* b1  = (const float*)d_in[3];
    const float* W2  = (const float*)d_in[4];
    const float* b2  = (const float*)d_in[5];
    const float* W3  = (const float*)d_in[6];
    const float* b3  = (const float*)d_in[7];

    float* out       = (float*)d_out;
    float* pos_s_out = out + (size_t)BATCH * MCTR * OUTD;

    cudaFuncSetAttribute(fpsfeat_kernel,
                         cudaFuncAttributeMaxDynamicSharedMemorySize, (int)sizeof(MSmem));
    cudaFuncSetAttribute(center_kernel,
                         cudaFuncAttributeMaxDynamicSharedMemorySize, (int)sizeof(CKS));

    fpsfeat_kernel<<<FPS_BLOCKS + FEAT_BLOCKS, 256, sizeof(MSmem)>>>(
        pos, pos_s_out, x, W1);
    center_kernel<<<BATCH * MCTR / 2, 256, sizeof(CKS)>>>(
        pos, W1, b1, W2, b2, W3, b3, out);
}

// round 9
// speedup vs baseline: 1.3491x; 1.0298x over previous
#include <cuda_runtime.h>
#include <cuda_bf16.h>
#include <cstdint>

#define NPTS 4096
#define BATCH 16
#define MCTR 1024
#define KNBR 64
#define OUTD 128
#define R2C  0.04f
#define CANDC 512

#define FPS_BLOCKS 16
#define FEAT_ROWS 128
#define FEAT_BLOCKS ((BATCH * NPTS) / FEAT_ROWS)   // 512
#define PREP_BLOCK (FPS_BLOCKS + FEAT_BLOCKS)      // weight-split block

#define AST 36   // padded u32 stride for bf16-pair tiles (conflict-free frags)

typedef unsigned long long ull;
typedef unsigned int u32;
typedef unsigned short u16;

// ---------------- device scratch ----------------
__device__ int   g_idx[BATCH * MCTR];
__device__ float g_feat[(size_t)BATCH * NPTS * 64];   // x @ W1[0:64,:]
__device__ u32   g_W2h[64 * 32],  g_W2l[64 * 32];     // W2^T bf16-pairs [n][k/2]
__device__ u32   g_W3h[128 * 32], g_W3l[128 * 32];    // W3^T bf16-pairs

// ---------------- f32x2 helpers ----------------
__device__ __forceinline__ ull fma2(ull a, ull b, ull c) {
    ull d; asm("fma.rn.f32x2 %0, %1, %2, %3;" : "=l"(d) : "l"(a), "l"(b), "l"(c));
    return d;
}
__device__ __forceinline__ ull pack2(float lo, float hi) {
    ull d; asm("mov.b64 %0, {%1, %2};" : "=l"(d) : "f"(lo), "f"(hi)); return d;
}
__device__ __forceinline__ float2 unpack2(ull v) {
    float2 r; asm("mov.b64 {%0, %1}, %2;" : "=f"(r.x), "=f"(r.y) : "l"(v)); return r;
}

// ---------------- mma.sync m16n8k16 bf16 ----------------
__device__ __forceinline__ void mma16816(float* c, u32 a0, u32 a1, u32 a2, u32 a3,
                                         u32 b0, u32 b1) {
    asm volatile(
        "mma.sync.aligned.m16n8k16.row.col.f32.bf16.bf16.f32 "
        "{%0,%1,%2,%3}, {%4,%5,%6,%7}, {%8,%9}, {%0,%1,%2,%3};"
        : "+f"(c[0]), "+f"(c[1]), "+f"(c[2]), "+f"(c[3])
        : "r"(a0), "r"(a1), "r"(a2), "r"(a3), "r"(b0), "r"(b1));
}

__device__ __forceinline__ void split_bf16(float v, u16& hi, u16& lo) {
    __nv_bfloat16 bh = __float2bfloat16(v);
    float r = v - __bfloat162float(bh);
    __nv_bfloat16 bl = __float2bfloat16(r);
    hi = __bfloat16_as_ushort(bh);
    lo = __bfloat16_as_ushort(bl);
}
__device__ __forceinline__ u32 split_pack_hi(float v0, float v1) {
    u16 h0, l0, h1, l1;
    split_bf16(v0, h0, l0); split_bf16(v1, h1, l1);
    return (u32)h0 | ((u32)h1 << 16);
}
__device__ __forceinline__ u32 split_pack_lo(float v0, float v1) {
    u16 h0, l0, h1, l1;
    split_bf16(v0, h0, l0); split_bf16(v1, h1, l1);
    return (u32)l0 | ((u32)l1 << 16);
}

// =========================================================================
// fpsfeat: blocks 0..15 FPS; 16..527 feat; 528 weight-split prep.
// 512 threads per block.
// =========================================================================
struct alignas(16) MSmem {
    union {
        struct {
            float px[NPTS], py[NPTS], pz[NPTS];
            ull   part[2][16];
        } fps;
        struct {
            float xx[FEAT_ROWS][65];
            float w[64][64];
        } feat;
    } u;
};

__global__ __launch_bounds__(512) void fpsfeat_kernel(
    const float* __restrict__ pos, float* __restrict__ pos_s_out,
    const float* __restrict__ x,   const float* __restrict__ W1,
    const float* __restrict__ W2,  const float* __restrict__ W3)
{
    extern __shared__ unsigned char smraw[];
    MSmem& sm = *reinterpret_cast<MSmem*>(smraw);
    int tid = threadIdx.x;

    if (blockIdx.x < FPS_BLOCKS) {
        // ------------------------- FPS -------------------------
        auto& S = sm.u.fps;
        int b = blockIdx.x;
        const float* pb = pos + (size_t)b * NPTS * 3;

        float px[8], py[8], pz[8], dst[8];
#pragma unroll
        for (int u = 0; u < 8; u++) {
            int i = tid + u * 512;
            float X = pb[i * 3 + 0], Y = pb[i * 3 + 1], Z = pb[i * 3 + 2];
            S.px[i] = X; S.py[i] = Y; S.pz[i] = Z;
            px[u] = X; py[u] = Y; pz[u] = Z;
            dst[u] = 1e10f;
        }
        __syncthreads();

        int   last = 0;
        float lx = S.px[0], ly = S.py[0], lz = S.pz[0];

        for (int m = 0; m < MCTR; m++) {
            if (tid == 0) {
                g_idx[b * MCTR + m] = last;
                float* po = pos_s_out + ((size_t)(b * MCTR + m)) * 3;
                po[0] = lx; po[1] = ly; po[2] = lz;
            }
            float bv = -1.0f; int bi = 0;
#pragma unroll
            for (int u = 0; u < 8; u++) {
                float dx = px[u] - lx, dy = py[u] - ly, dz = pz[u] - lz;
                float d  = fmaf(dx, dx, fmaf(dy, dy, dz * dz));
                float nd = fminf(dst[u], d);
                dst[u] = nd;
                int gi = tid + u * 512;
                if (nd > bv) { bv = nd; bi = gi; }
            }
            unsigned bvb  = __float_as_uint(bv);
            unsigned wmax = __reduce_max_sync(0xffffffffu, bvb);
            unsigned cand = (bvb == wmax) ? (unsigned)bi : 0xffffffffu;
            unsigned wbi  = __reduce_min_sync(0xffffffffu, cand);
            ull key = ((ull)wmax << 32) | (unsigned)(~wbi);
            if ((tid & 31) == 0) S.part[m & 1][tid >> 5] = key;
            __syncthreads();
            ull best = S.part[m & 1][0];
#pragma unroll
            for (int w = 1; w < 16; w++) {
                ull k2 = S.part[m & 1][w];
                if (k2 > best) best = k2;
            }
            last = (int)(~(unsigned)best);
            lx = S.px[last]; ly = S.py[last]; lz = S.pz[last];
        }
    } else if (blockIdx.x < PREP_BLOCK) {
        // ------------------------- feat -------------------------
        auto& S = sm.u.feat;
        size_t rbase = (size_t)(blockIdx.x - FPS_BLOCKS) * FEAT_ROWS;

        for (int i = tid; i < 64 * 64; i += 512) S.w[i >> 6][i & 63] = W1[i];
        for (int i = tid; i < FEAT_ROWS * 64; i += 512)
            S.xx[i >> 6][i & 63] = x[rbase * 64 + i];
        __syncthreads();

        int r = tid >> 2, q = tid & 3;     // 128 rows x 16 channels
        ull acc[8];
#pragma unroll
        for (int c = 0; c < 8; c++) acc[c] = 0ull;
        for (int k = 0; k < 64; k++) {
            float xv = S.xx[r][k];
            ull xb = pack2(xv, xv);
            const ulonglong2* wp = reinterpret_cast<const ulonglong2*>(&S.w[k][q * 16]);
            ulonglong2 w0 = wp[0], w1 = wp[1], w2 = wp[2], w3 = wp[3];
            acc[0] = fma2(xb, w0.x, acc[0]); acc[1] = fma2(xb, w0.y, acc[1]);
            acc[2] = fma2(xb, w1.x, acc[2]); acc[3] = fma2(xb, w1.y, acc[3]);
            acc[4] = fma2(xb, w2.x, acc[4]); acc[5] = fma2(xb, w2.y, acc[5]);
            acc[6] = fma2(xb, w3.x, acc[6]); acc[7] = fma2(xb, w3.y, acc[7]);
        }
        float* go = g_feat + (rbase + r) * 64 + q * 16;
#pragma unroll
        for (int c = 0; c < 4; c++) {
            float2 a = unpack2(acc[c * 2]), bq = unpack2(acc[c * 2 + 1]);
            *reinterpret_cast<float4*>(go + c * 4) = make_float4(a.x, a.y, bq.x, bq.y);
        }
    } else {
        // ------------------ weight split prep (once) ------------------
        for (int i = tid; i < 64 * 64; i += 512) {     // W2: n=i>>6, k=i&63
            int nn = i >> 6, k = i & 63;
            u16 hi, lo;
            split_bf16(W2[k * 64 + nn], hi, lo);
            int w = nn * 32 + (k >> 1);
            ((u16*)g_W2h)[w * 2 + (k & 1)] = hi;
            ((u16*)g_W2l)[w * 2 + (k & 1)] = lo;
        }
        for (int i = tid; i < 128 * 64; i += 512) {    // W3
            int nn = i >> 6, k = i & 63;
            u16 hi, lo;
            split_bf16(W3[k * 128 + nn], hi, lo);
            int w = nn * 32 + (k >> 1);
            ((u16*)g_W3h)[w * 2 + (k & 1)] = hi;
            ((u16*)g_W3l)[w * 2 + (k & 1)] = lo;
        }
    }
}

// =========================================================================
// center kernel: 2 centers/block (128 A-rows), 256 threads = 8 warps.
// =========================================================================
struct alignas(16) CKS {
    ull   keys[2 * CANDC];        // 8 KB
    u32   Ah[128 * AST];          // 18.4 KB
    u32   Al[128 * AST];
    u32   W2h[64 * AST];          // 9.2 KB
    u32   W2l[64 * AST];
    u32   W3h[128 * AST];         // 18.4 KB
    u32   W3l[128 * AST];
    float pool[8][132];
    float b1s[64], b2s[64], b3s[128];
    float w1b[3 * 64];
    float rel[128 * 3];
    int   nbr[128];
    float ctr[6];
    int   cnt[2], nvv[2];
};

__global__ __launch_bounds__(256, 2) void center_kernel(
    const float* __restrict__ pos,
    const float* __restrict__ W1, const float* __restrict__ b1,
    const float* __restrict__ b2, const float* __restrict__ b3,
    float* __restrict__ out)
{
    extern __shared__ unsigned char smraw[];
    CKS& s = *reinterpret_cast<CKS*>(smraw);

    int tid = threadIdx.x;
    int wid = tid >> 5, lane = tid & 31;
    int blk = blockIdx.x;
    int c0  = blk * 2;
    int b   = c0 >> 10;
    const float* pb = pos + (size_t)b * NPTS * 3;

    if (tid == 0) {
        s.cnt[0] = 0; s.cnt[1] = 0;
        int ci0 = g_idx[c0], ci1 = g_idx[c0 + 1];
        s.ctr[0] = pb[ci0 * 3 + 0]; s.ctr[1] = pb[ci0 * 3 + 1]; s.ctr[2] = pb[ci0 * 3 + 2];
        s.ctr[3] = pb[ci1 * 3 + 0]; s.ctr[4] = pb[ci1 * 3 + 1]; s.ctr[5] = pb[ci1 * 3 + 2];
    }
    if (tid < 128) {
        s.nbr[tid] = 0;
        s.rel[tid * 3 + 0] = 0.f; s.rel[tid * 3 + 1] = 0.f; s.rel[tid * 3 + 2] = 0.f;
    }

    // ---- weight copy (pre-split u32s, L2-resident) ----
    for (int i = tid; i < 64 * 32; i += 256) {
        int nn = i >> 5, kk = i & 31;
        s.W2h[nn * AST + kk] = g_W2h[i];
        s.W2l[nn * AST + kk] = g_W2l[i];
    }
    for (int i = tid; i < 128 * 32; i += 256) {
        int nn = i >> 5, kk = i & 31;
        s.W3h[nn * AST + kk] = g_W3h[i];
        s.W3l[nn * AST + kk] = g_W3l[i];
    }
    if (tid < 192) s.w1b[tid] = W1[64 * 64 + tid];
    if (tid < 64)       { s.b1s[tid] = b1[tid]; s.b2s[tid] = b2[tid]; }
    else if (tid < 192) s.b3s[tid - 64] = b3[tid - 64];
    __syncthreads();
    float cx0 = s.ctr[0], cy0 = s.ctr[1], cz0 = s.ctr[2];
    float cx1 = s.ctr[3], cy1 = s.ctr[4], cz1 = s.ctr[5];

    // ---- phase 1: shared candidate scan ----
    for (int i = tid; i < NPTS; i += 256) {
        float X = pb[i * 3 + 0], Y = pb[i * 3 + 1], Z = pb[i * 3 + 2];
        float dx0 = X - cx0, dy0 = Y - cy0, dz0 = Z - cz0;
        float d20 = fmaf(dx0, dx0, fmaf(dy0, dy0, dz0 * dz0));
        if (d20 <= R2C) {
            int p = atomicAdd(&s.cnt[0], 1);
            if (p < CANDC) s.keys[p] = ((ull)__float_as_uint(d20) << 32) | (unsigned)i;
        }
        float dx1 = X - cx1, dy1 = Y - cy1, dz1 = Z - cz1;
        float d21 = fmaf(dx1, dx1, fmaf(dy1, dy1, dz1 * dz1));
        if (d21 <= R2C) {
            int p = atomicAdd(&s.cnt[1], 1);
            if (p < CANDC) s.keys[CANDC + p] = ((ull)__float_as_uint(d21) << 32) | (unsigned)i;
        }
    }
    __syncthreads();

    // ---- phase 2: rank-count selection ----
    for (int cc = 0; cc < 2; cc++) {
        int n  = min(s.cnt[cc], CANDC);
        int nv = min(n, KNBR);
        const ull* kk = s.keys + cc * CANDC;
        float ccx = cc ? cx1 : cx0, ccy = cc ? cy1 : cy0, ccz = cc ? cz1 : cz0;
        ull myk[2]; int rnk[2];
#pragma unroll
        for (int t = 0; t < 2; t++) {
            int i = tid + t * 256;
            myk[t] = (i < n) ? kk[i] : ~0ull;
            rnk[t] = 0;
        }
        for (int j = 0; j < n; j++) {
            ull kj = kk[j];
#pragma unroll
            for (int t = 0; t < 2; t++) rnk[t] += (kj < myk[t]) ? 1 : 0;
        }
#pragma unroll
        for (int t = 0; t < 2; t++) {
            int i = tid + t * 256;
            if (i < n && rnk[t] < KNBR) {
                int idx = (int)(myk[t] & 0xffffffffu);
                int slot = cc * 64 + rnk[t];
                s.nbr[slot] = idx;
                s.rel[slot * 3 + 0] = pb[idx * 3 + 0] - ccx;
                s.rel[slot * 3 + 1] = pb[idx * 3 + 1] - ccy;
                s.rel[slot * 3 + 2] = pb[idx * 3 + 2] - ccz;
            }
        }
        if (tid == 0) s.nvv[cc] = nv;
    }
    __syncthreads();

    int nv0 = s.nvv[0], nv1 = s.nvv[1];

    // ---- h1 (scalar fp32) -> split bf16 A tile ----
    {
        int row = tid >> 1, half = tid & 1;
        int j = s.nbr[row];
        const float4* gr = reinterpret_cast<const float4*>(
            g_feat + ((size_t)(b * NPTS + j)) * 64 + half * 32);
        float rx = s.rel[row * 3 + 0], ry = s.rel[row * 3 + 1], rz = s.rel[row * 3 + 2];
#pragma unroll
        for (int c4 = 0; c4 < 8; c4++) {
            float4 g = gr[c4];
            float v[4] = {g.x, g.y, g.z, g.w};
            float o[4];
#pragma unroll
            for (int c = 0; c < 4; c++) {
                int ch = half * 32 + c4 * 4 + c;
                float t = v[c];
                t = fmaf(rx, s.w1b[ch], t);
                t = fmaf(ry, s.w1b[64 + ch], t);
                t = fmaf(rz, s.w1b[128 + ch], t);
                o[c] = fmaxf(t + s.b1s[ch], 0.f);
            }
            int w = row * AST + half * 16 + c4 * 2;
            s.Ah[w]     = split_pack_hi(o[0], o[1]);
            s.Al[w]     = split_pack_lo(o[0], o[1]);
            s.Ah[w + 1] = split_pack_hi(o[2], o[3]);
            s.Al[w + 1] = split_pack_lo(o[2], o[3]);
        }
    }
    __syncthreads();

    int r0 = wid * 16 + (lane >> 2);
    int lp = lane & 3;

    // ================= layer 2: h2[128,64] = A @ W2^T =================
    {
        float acc[8][4];
#pragma unroll
        for (int nt = 0; nt < 8; nt++)
#pragma unroll
            for (int c = 0; c < 4; c++) acc[nt][c] = 0.f;

#pragma unroll
        for (int kt = 0; kt < 4; kt++) {
            int aw = kt * 8 + lp;
            u32 ah0 = s.Ah[r0 * AST + aw],       ah1 = s.Ah[(r0 + 8) * AST + aw];
            u32 ah2 = s.Ah[r0 * AST + aw + 4],   ah3 = s.Ah[(r0 + 8) * AST + aw + 4];
            u32 al0 = s.Al[r0 * AST + aw],       al1 = s.Al[(r0 + 8) * AST + aw];
            u32 al2 = s.Al[r0 * AST + aw + 4],   al3 = s.Al[(r0 + 8) * AST + aw + 4];
#pragma unroll
            for (int nt = 0; nt < 8; nt++) {
                int n = nt * 8 + (lane >> 2);
                u32 bh0 = s.W2h[n * AST + aw], bh1 = s.W2h[n * AST + aw + 4];
                u32 bl0 = s.W2l[n * AST + aw], bl1 = s.W2l[n * AST + aw + 4];
                mma16816(acc[nt], ah0, ah1, ah2, ah3, bh0, bh1);
                mma16816(acc[nt], ah0, ah1, ah2, ah3, bl0, bl1);
                mma16816(acc[nt], al0, al1, al2, al3, bh0, bh1);
            }
        }
#pragma unroll
        for (int nt = 0; nt < 8; nt++) {
            int cn = nt * 8 + lp * 2;
            float bb0 = s.b2s[cn], bb1 = s.b2s[cn + 1];
            float v0 = fmaxf(acc[nt][0] + bb0, 0.f);
            float v1 = fmaxf(acc[nt][1] + bb1, 0.f);
            float v2 = fmaxf(acc[nt][2] + bb0, 0.f);
            float v3 = fmaxf(acc[nt][3] + bb1, 0.f);
            int w = nt * 4 + lp;
            s.Ah[r0 * AST + w]       = split_pack_hi(v0, v1);
            s.Al[r0 * AST + w]       = split_pack_lo(v0, v1);
            s.Ah[(r0 + 8) * AST + w] = split_pack_hi(v2, v3);
            s.Al[(r0 + 8) * AST + w] = split_pack_lo(v2, v3);
        }
    }
    __syncwarp();

    // ================= layer 3: out[128,128] = A @ W3^T + masked max ====
    {
        int rin = (wid & 3) * 16 + (lane >> 2);
        int nv  = (wid >> 2) ? nv1 : nv0;
        bool va = rin < nv, vb = (rin + 8) < nv;

        for (int hhalf = 0; hhalf < 2; hhalf++) {
            float acc[8][4];
#pragma unroll
            for (int nt = 0; nt < 8; nt++)
#pragma unroll
                for (int c = 0; c < 4; c++) acc[nt][c] = 0.f;

#pragma unroll
            for (int kt = 0; kt < 4; kt++) {
                int aw = kt * 8 + lp;
                u32 ah0 = s.Ah[r0 * AST + aw],     ah1 = s.Ah[(r0 + 8) * AST + aw];
                u32 ah2 = s.Ah[r0 * AST + aw + 4], ah3 = s.Ah[(r0 + 8) * AST + aw + 4];
                u32 al0 = s.Al[r0 * AST + aw],     al1 = s.Al[(r0 + 8) * AST + aw];
                u32 al2 = s.Al[r0 * AST + aw + 4], al3 = s.Al[(r0 + 8) * AST + aw + 4];
#pragma unroll
                for (int nt = 0; nt < 8; nt++) {
                    int n = hhalf * 64 + nt * 8 + (lane >> 2);
                    u32 bh0 = s.W3h[n * AST + aw], bh1 = s.W3h[n * AST + aw + 4];
                    u32 bl0 = s.W3l[n * AST + aw], bl1 = s.W3l[n * AST + aw + 4];
                    mma16816(acc[nt], ah0, ah1, ah2, ah3, bh0, bh1);
                    mma16816(acc[nt], ah0, ah1, ah2, ah3, bl0, bl1);
                    mma16816(acc[nt], al0, al1, al2, al3, bh0, bh1);
                }
            }
#pragma unroll
            for (int nt = 0; nt < 8; nt++) {
                float m0 = fmaxf(va ? acc[nt][0] : -1e30f, vb ? acc[nt][2] : -1e30f);
                float m1 = fmaxf(va ? acc[nt][1] : -1e30f, vb ? acc[nt][3] : -1e30f);
#pragma unroll
                for (int off = 16; off >= 4; off >>= 1) {
                    m0 = fmaxf(m0, __shfl_down_sync(0xffffffffu, m0, off));
                    m1 = fmaxf(m1, __shfl_down_sync(0xffffffffu, m1, off));
                }
                if (lane < 4) {
                    int cn = hhalf * 64 + nt * 8 + lane * 2;
                    s.pool[wid][cn]     = m0;
                    s.pool[wid][cn + 1] = m1;
                }
            }
        }
    }
    __syncthreads();

    // ---- combine 4 warps per center + bias ----
    {
        int center = tid >> 7, ch = tid & 127;
        int w0 = center * 4;
        float v = s.pool[w0][ch];
        v = fmaxf(v, s.pool[w0 + 1][ch]);
        v = fmaxf(v, s.pool[w0 + 2][ch]);
        v = fmaxf(v, s.pool[w0 + 3][ch]);
        out[(size_t)(c0 + center) * OUTD + ch] = v + s.b3s[ch];
    }
}

// =========================================================================
extern "C" void kernel_launch(void* const* d_in, const int* in_sizes, int n_in,
                              void* d_out, int out_size)
{
    const float* x   = (const float*)d_in[0];
    const float* pos = (const float*)d_in[1];
    const float* W1  = (const float*)d_in[2];
    const float* b1  = (const float*)d_in[3];
    const float* W2  = (const float*)d_in[4];
    const float* b2  = (const float*)d_in[5];
    const float* W3  = (const float*)d_in[6];
    const float* b3  = (const float*)d_in[7];

    float* out       = (float*)d_out;
    float* pos_s_out = out + (size_t)BATCH * MCTR * OUTD;

    cudaFuncSetAttribute(fpsfeat_kernel,
                         cudaFuncAttributeMaxDynamicSharedMemorySize, (int)sizeof(MSmem));
    cudaFuncSetAttribute(center_kernel,
                         cudaFuncAttributeMaxDynamicSharedMemorySize, (int)sizeof(CKS));

    fpsfeat_kernel<<<PREP_BLOCK + 1, 512, sizeof(MSmem)>>>(
        pos, pos_s_out, x, W1, W2, W3);
    center_kernel<<<BATCH * MCTR / 2, 256, sizeof(CKS)>>>(
        pos, W1, b1, b2, b3, out);
}

// round 10
// speedup vs baseline: 1.5497x; 1.1487x over previous
#include <cuda_runtime.h>
#include <cuda_bf16.h>
#include <cstdint>

#define NPTS 4096
#define BATCH 16
#define MCTR 1024
#define KNBR 64
#define OUTD 128
#define R2C  0.04f
#define CANDC 512

#define FPS_BLOCKS 16
#define FEAT_ROWS 64
#define FEAT_BLOCKS ((BATCH * NPTS) / FEAT_ROWS)   // 1024
#define PREP_BLOCK (FPS_BLOCKS + FEAT_BLOCKS)      // weight-split block

#define AST 36   // padded u32 stride for bf16-pair tiles (conflict-free frags)

typedef unsigned long long ull;
typedef unsigned int u32;
typedef unsigned short u16;

// ---------------- device scratch ----------------
__device__ int   g_idx[BATCH * MCTR];
__device__ float g_feat[(size_t)BATCH * NPTS * 64];   // x @ W1[0:64,:]
__device__ u32   g_W2h[64 * 32],  g_W2l[64 * 32];     // W2^T bf16-pairs [n][k/2]
__device__ u32   g_W3h[128 * 32], g_W3l[128 * 32];    // W3^T bf16-pairs

// ---------------- f32x2 helpers ----------------
__device__ __forceinline__ ull fma2(ull a, ull b, ull c) {
    ull d; asm("fma.rn.f32x2 %0, %1, %2, %3;" : "=l"(d) : "l"(a), "l"(b), "l"(c));
    return d;
}
__device__ __forceinline__ ull pack2(float lo, float hi) {
    ull d; asm("mov.b64 %0, {%1, %2};" : "=l"(d) : "f"(lo), "f"(hi)); return d;
}
__device__ __forceinline__ float2 unpack2(ull v) {
    float2 r; asm("mov.b64 {%0, %1}, %2;" : "=f"(r.x), "=f"(r.y) : "l"(v)); return r;
}

// ---------------- mma.sync m16n8k16 bf16 ----------------
__device__ __forceinline__ void mma16816(float* c, u32 a0, u32 a1, u32 a2, u32 a3,
                                         u32 b0, u32 b1) {
    asm volatile(
        "mma.sync.aligned.m16n8k16.row.col.f32.bf16.bf16.f32 "
        "{%0,%1,%2,%3}, {%4,%5,%6,%7}, {%8,%9}, {%0,%1,%2,%3};"
        : "+f"(c[0]), "+f"(c[1]), "+f"(c[2]), "+f"(c[3])
        : "r"(a0), "r"(a1), "r"(a2), "r"(a3), "r"(b0), "r"(b1));
}

__device__ __forceinline__ void split_bf16(float v, u16& hi, u16& lo) {
    __nv_bfloat16 bh = __float2bfloat16(v);
    float r = v - __bfloat162float(bh);
    __nv_bfloat16 bl = __float2bfloat16(r);
    hi = __bfloat16_as_ushort(bh);
    lo = __bfloat16_as_ushort(bl);
}
__device__ __forceinline__ u32 split_pack_hi(float v0, float v1) {
    u16 h0, l0, h1, l1;
    split_bf16(v0, h0, l0); split_bf16(v1, h1, l1);
    return (u32)h0 | ((u32)h1 << 16);
}
__device__ __forceinline__ u32 split_pack_lo(float v0, float v1) {
    u16 h0, l0, h1, l1;
    split_bf16(v0, h0, l0); split_bf16(v1, h1, l1);
    return (u32)l0 | ((u32)l1 << 16);
}

// =========================================================================
// fpsfeat: blocks 0..15 FPS (256 thr, 16 pts/thr — R7 measured-fast config);
// 16..1039 feat (64 rows); 1040 weight-split prep. 256 threads per block.
// =========================================================================
struct alignas(16) MSmem {
    union {
        struct {
            float px[NPTS], py[NPTS], pz[NPTS];
            ull   part[2][8];
        } fps;
        struct {
            float xx[FEAT_ROWS][65];
            float w[64][64];
        } feat;
    } u;
};

__global__ __launch_bounds__(256) void fpsfeat_kernel(
    const float* __restrict__ pos, float* __restrict__ pos_s_out,
    const float* __restrict__ x,   const float* __restrict__ W1,
    const float* __restrict__ W2,  const float* __restrict__ W3)
{
    extern __shared__ unsigned char smraw[];
    MSmem& sm = *reinterpret_cast<MSmem*>(smraw);
    int tid = threadIdx.x;

    if (blockIdx.x < FPS_BLOCKS) {
        // ------------------------- FPS -------------------------
        auto& S = sm.u.fps;
        int b = blockIdx.x;
        const float* pb = pos + (size_t)b * NPTS * 3;

        float px[16], py[16], pz[16], dst[16];
#pragma unroll
        for (int u = 0; u < 16; u++) {
            int i = tid + u * 256;
            float X = pb[i * 3 + 0], Y = pb[i * 3 + 1], Z = pb[i * 3 + 2];
            S.px[i] = X; S.py[i] = Y; S.pz[i] = Z;
            px[u] = X; py[u] = Y; pz[u] = Z;
            dst[u] = 1e10f;
        }
        __syncthreads();

        int   last = 0;
        float lx = S.px[0], ly = S.py[0], lz = S.pz[0];

        for (int m = 0; m < MCTR; m++) {
            if (tid == 0) {
                g_idx[b * MCTR + m] = last;
                float* po = pos_s_out + ((size_t)(b * MCTR + m)) * 3;
                po[0] = lx; po[1] = ly; po[2] = lz;
            }
            float bv = -1.0f; int bi = 0;
#pragma unroll
            for (int u = 0; u < 16; u++) {
                float dx = px[u] - lx, dy = py[u] - ly, dz = pz[u] - lz;
                float d  = fmaf(dx, dx, fmaf(dy, dy, dz * dz));
                float nd = fminf(dst[u], d);
                dst[u] = nd;
                int gi = tid + u * 256;
                if (nd > bv) { bv = nd; bi = gi; }
            }
            unsigned bvb  = __float_as_uint(bv);
            unsigned wmax = __reduce_max_sync(0xffffffffu, bvb);
            unsigned cand = (bvb == wmax) ? (unsigned)bi : 0xffffffffu;
            unsigned wbi  = __reduce_min_sync(0xffffffffu, cand);
            ull key = ((ull)wmax << 32) | (unsigned)(~wbi);
            if ((tid & 31) == 0) S.part[m & 1][tid >> 5] = key;
            __syncthreads();
            ull best = S.part[m & 1][0];
#pragma unroll
            for (int w = 1; w < 8; w++) {
                ull k2 = S.part[m & 1][w];
                if (k2 > best) best = k2;
            }
            last = (int)(~(unsigned)best);
            lx = S.px[last]; ly = S.py[last]; lz = S.pz[last];
        }
    } else if (blockIdx.x < PREP_BLOCK) {
        // ------------------------- feat -------------------------
        auto& S = sm.u.feat;
        size_t rbase = (size_t)(blockIdx.x - FPS_BLOCKS) * FEAT_ROWS;

        for (int i = tid; i < 64 * 64; i += 256) S.w[i >> 6][i & 63] = W1[i];
        for (int i = tid; i < FEAT_ROWS * 64; i += 256)
            S.xx[i >> 6][i & 63] = x[rbase * 64 + i];
        __syncthreads();

        int r = tid >> 2, q = tid & 3;     // 64 rows x 16 channels
        ull acc[8];
#pragma unroll
        for (int c = 0; c < 8; c++) acc[c] = 0ull;
        for (int k = 0; k < 64; k++) {
            float xv = S.xx[r][k];
            ull xb = pack2(xv, xv);
            const ulonglong2* wp = reinterpret_cast<const ulonglong2*>(&S.w[k][q * 16]);
            ulonglong2 w0 = wp[0], w1 = wp[1], w2 = wp[2], w3 = wp[3];
            acc[0] = fma2(xb, w0.x, acc[0]); acc[1] = fma2(xb, w0.y, acc[1]);
            acc[2] = fma2(xb, w1.x, acc[2]); acc[3] = fma2(xb, w1.y, acc[3]);
            acc[4] = fma2(xb, w2.x, acc[4]); acc[5] = fma2(xb, w2.y, acc[5]);
            acc[6] = fma2(xb, w3.x, acc[6]); acc[7] = fma2(xb, w3.y, acc[7]);
        }
        float* go = g_feat + (rbase + r) * 64 + q * 16;
#pragma unroll
        for (int c = 0; c < 4; c++) {
            float2 a = unpack2(acc[c * 2]), bq = unpack2(acc[c * 2 + 1]);
            *reinterpret_cast<float4*>(go + c * 4) = make_float4(a.x, a.y, bq.x, bq.y);
        }
    } else {
        // ------------------ weight split prep (once) ------------------
        for (int i = tid; i < 64 * 64; i += 256) {     // W2: n=i>>6, k=i&63
            int nn = i >> 6, k = i & 63;
            u16 hi, lo;
            split_bf16(W2[k * 64 + nn], hi, lo);
            int w = nn * 32 + (k >> 1);
            ((u16*)g_W2h)[w * 2 + (k & 1)] = hi;
            ((u16*)g_W2l)[w * 2 + (k & 1)] = lo;
        }
        for (int i = tid; i < 128 * 64; i += 256) {    // W3
            int nn = i >> 6, k = i & 63;
            u16 hi, lo;
            split_bf16(W3[k * 128 + nn], hi, lo);
            int w = nn * 32 + (k >> 1);
            ((u16*)g_W3h)[w * 2 + (k & 1)] = hi;
            ((u16*)g_W3l)[w * 2 + (k & 1)] = lo;
        }
    }
}

// =========================================================================
// center kernel: 2 centers/block (128 A-rows), 256 threads = 8 warps.
// (unchanged from R9 — measured 745 us)
// =========================================================================
struct alignas(16) CKS {
    ull   keys[2 * CANDC];        // 8 KB
    u32   Ah[128 * AST];          // 18.4 KB
    u32   Al[128 * AST];
    u32   W2h[64 * AST];          // 9.2 KB
    u32   W2l[64 * AST];
    u32   W3h[128 * AST];         // 18.4 KB
    u32   W3l[128 * AST];
    float pool[8][132];
    float b1s[64], b2s[64], b3s[128];
    float w1b[3 * 64];
    float rel[128 * 3];
    int   nbr[128];
    float ctr[6];
    int   cnt[2], nvv[2];
};

__global__ __launch_bounds__(256, 2) void center_kernel(
    const float* __restrict__ pos,
    const float* __restrict__ W1, const float* __restrict__ b1,
    const float* __restrict__ b2, const float* __restrict__ b3,
    float* __restrict__ out)
{
    extern __shared__ unsigned char smraw[];
    CKS& s = *reinterpret_cast<CKS*>(smraw);

    int tid = threadIdx.x;
    int wid = tid >> 5, lane = tid & 31;
    int blk = blockIdx.x;
    int c0  = blk * 2;
    int b   = c0 >> 10;
    const float* pb = pos + (size_t)b * NPTS * 3;

    if (tid == 0) {
        s.cnt[0] = 0; s.cnt[1] = 0;
        int ci0 = g_idx[c0], ci1 = g_idx[c0 + 1];
        s.ctr[0] = pb[ci0 * 3 + 0]; s.ctr[1] = pb[ci0 * 3 + 1]; s.ctr[2] = pb[ci0 * 3 + 2];
        s.ctr[3] = pb[ci1 * 3 + 0]; s.ctr[4] = pb[ci1 * 3 + 1]; s.ctr[5] = pb[ci1 * 3 + 2];
    }
    if (tid < 128) {
        s.nbr[tid] = 0;
        s.rel[tid * 3 + 0] = 0.f; s.rel[tid * 3 + 1] = 0.f; s.rel[tid * 3 + 2] = 0.f;
    }

    // ---- weight copy (pre-split u32s, L2-resident) ----
    for (int i = tid; i < 64 * 32; i += 256) {
        int nn = i >> 5, kk = i & 31;
        s.W2h[nn * AST + kk] = g_W2h[i];
        s.W2l[nn * AST + kk] = g_W2l[i];
    }
    for (int i = tid; i < 128 * 32; i += 256) {
        int nn = i >> 5, kk = i & 31;
        s.W3h[nn * AST + kk] = g_W3h[i];
        s.W3l[nn * AST + kk] = g_W3l[i];
    }
    if (tid < 192) s.w1b[tid] = W1[64 * 64 + tid];
    if (tid < 64)       { s.b1s[tid] = b1[tid]; s.b2s[tid] = b2[tid]; }
    else if (tid < 192) s.b3s[tid - 64] = b3[tid - 64];
    __syncthreads();
    float cx0 = s.ctr[0], cy0 = s.ctr[1], cz0 = s.ctr[2];
    float cx1 = s.ctr[3], cy1 = s.ctr[4], cz1 = s.ctr[5];

    // ---- phase 1: shared candidate scan ----
    for (int i = tid; i < NPTS; i += 256) {
        float X = pb[i * 3 + 0], Y = pb[i * 3 + 1], Z = pb[i * 3 + 2];
        float dx0 = X - cx0, dy0 = Y - cy0, dz0 = Z - cz0;
        float d20 = fmaf(dx0, dx0, fmaf(dy0, dy0, dz0 * dz0));
        if (d20 <= R2C) {
            int p = atomicAdd(&s.cnt[0], 1);
            if (p < CANDC) s.keys[p] = ((ull)__float_as_uint(d20) << 32) | (unsigned)i;
        }
        float dx1 = X - cx1, dy1 = Y - cy1, dz1 = Z - cz1;
        float d21 = fmaf(dx1, dx1, fmaf(dy1, dy1, dz1 * dz1));
        if (d21 <= R2C) {
            int p = atomicAdd(&s.cnt[1], 1);
            if (p < CANDC) s.keys[CANDC + p] = ((ull)__float_as_uint(d21) << 32) | (unsigned)i;
        }
    }
    __syncthreads();

    // ---- phase 2: rank-count selection ----
    for (int cc = 0; cc < 2; cc++) {
        int n  = min(s.cnt[cc], CANDC);
        int nv = min(n, KNBR);
        const ull* kk = s.keys + cc * CANDC;
        float ccx = cc ? cx1 : cx0, ccy = cc ? cy1 : cy0, ccz = cc ? cz1 : cz0;
        ull myk[2]; int rnk[2];
#pragma unroll
        for (int t = 0; t < 2; t++) {
            int i = tid + t * 256;
            myk[t] = (i < n) ? kk[i] : ~0ull;
            rnk[t] = 0;
        }
        for (int j = 0; j < n; j++) {
            ull kj = kk[j];
#pragma unroll
            for (int t = 0; t < 2; t++) rnk[t] += (kj < myk[t]) ? 1 : 0;
        }
#pragma unroll
        for (int t = 0; t < 2; t++) {
            int i = tid + t * 256;
            if (i < n && rnk[t] < KNBR) {
                int idx = (int)(myk[t] & 0xffffffffu);
                int slot = cc * 64 + rnk[t];
                s.nbr[slot] = idx;
                s.rel[slot * 3 + 0] = pb[idx * 3 + 0] - ccx;
                s.rel[slot * 3 + 1] = pb[idx * 3 + 1] - ccy;
                s.rel[slot * 3 + 2] = pb[idx * 3 + 2] - ccz;
            }
        }
        if (tid == 0) s.nvv[cc] = nv;
    }
    __syncthreads();

    int nv0 = s.nvv[0], nv1 = s.nvv[1];

    // ---- h1 (scalar fp32) -> split bf16 A tile ----
    {
        int row = tid >> 1, half = tid & 1;
        int j = s.nbr[row];
        const float4* gr = reinterpret_cast<const float4*>(
            g_feat + ((size_t)(b * NPTS + j)) * 64 + half * 32);
        float rx = s.rel[row * 3 + 0], ry = s.rel[row * 3 + 1], rz = s.rel[row * 3 + 2];
#pragma unroll
        for (int c4 = 0; c4 < 8; c4++) {
            float4 g = gr[c4];
            float v[4] = {g.x, g.y, g.z, g.w};
            float o[4];
#pragma unroll
            for (int c = 0; c < 4; c++) {
                int ch = half * 32 + c4 * 4 + c;
                float t = v[c];
                t = fmaf(rx, s.w1b[ch], t);
                t = fmaf(ry, s.w1b[64 + ch], t);
                t = fmaf(rz, s.w1b[128 + ch], t);
                o[c] = fmaxf(t + s.b1s[ch], 0.f);
            }
            int w = row * AST + half * 16 + c4 * 2;
            s.Ah[w]     = split_pack_hi(o[0], o[1]);
            s.Al[w]     = split_pack_lo(o[0], o[1]);
            s.Ah[w + 1] = split_pack_hi(o[2], o[3]);
            s.Al[w + 1] = split_pack_lo(o[2], o[3]);
        }
    }
    __syncthreads();

    int r0 = wid * 16 + (lane >> 2);
    int lp = lane & 3;

    // ================= layer 2: h2[128,64] = A @ W2^T =================
    {
        float acc[8][4];
#pragma unroll
        for (int nt = 0; nt < 8; nt++)
#pragma unroll
            for (int c = 0; c < 4; c++) acc[nt][c] = 0.f;

#pragma unroll
        for (int kt = 0; kt < 4; kt++) {
            int aw = kt * 8 + lp;
            u32 ah0 = s.Ah[r0 * AST + aw],       ah1 = s.Ah[(r0 + 8) * AST + aw];
            u32 ah2 = s.Ah[r0 * AST + aw + 4],   ah3 = s.Ah[(r0 + 8) * AST + aw + 4];
            u32 al0 = s.Al[r0 * AST + aw],       al1 = s.Al[(r0 + 8) * AST + aw];
            u32 al2 = s.Al[r0 * AST + aw + 4],   al3 = s.Al[(r0 + 8) * AST + aw + 4];
#pragma unroll
            for (int nt = 0; nt < 8; nt++) {
                int n = nt * 8 + (lane >> 2);
                u32 bh0 = s.W2h[n * AST + aw], bh1 = s.W2h[n * AST + aw + 4];
                u32 bl0 = s.W2l[n * AST + aw], bl1 = s.W2l[n * AST + aw + 4];
                mma16816(acc[nt], ah0, ah1, ah2, ah3, bh0, bh1);
                mma16816(acc[nt], ah0, ah1, ah2, ah3, bl0, bl1);
                mma16816(acc[nt], al0, al1, al2, al3, bh0, bh1);
            }
        }
#pragma unroll
        for (int nt = 0; nt < 8; nt++) {
            int cn = nt * 8 + lp * 2;
            float bb0 = s.b2s[cn], bb1 = s.b2s[cn + 1];
            float v0 = fmaxf(acc[nt][0] + bb0, 0.f);
            float v1 = fmaxf(acc[nt][1] + bb1, 0.f);
            float v2 = fmaxf(acc[nt][2] + bb0, 0.f);
            float v3 = fmaxf(acc[nt][3] + bb1, 0.f);
            int w = nt * 4 + lp;
            s.Ah[r0 * AST + w]       = split_pack_hi(v0, v1);
            s.Al[r0 * AST + w]       = split_pack_lo(v0, v1);
            s.Ah[(r0 + 8) * AST + w] = split_pack_hi(v2, v3);
            s.Al[(r0 + 8) * AST + w] = split_pack_lo(v2, v3);
        }
    }
    __syncwarp();

    // ================= layer 3: out[128,128] = A @ W3^T + masked max ====
    {
        int rin = (wid & 3) * 16 + (lane >> 2);
        int nv  = (wid >> 2) ? nv1 : nv0;
        bool va = rin < nv, vb = (rin + 8) < nv;

        for (int hhalf = 0; hhalf < 2; hhalf++) {
            float acc[8][4];
#pragma unroll
            for (int nt = 0; nt < 8; nt++)
#pragma unroll
                for (int c = 0; c < 4; c++) acc[nt][c] = 0.f;

#pragma unroll
            for (int kt = 0; kt < 4; kt++) {
                int aw = kt * 8 + lp;
                u32 ah0 = s.Ah[r0 * AST + aw],     ah1 = s.Ah[(r0 + 8) * AST + aw];
                u32 ah2 = s.Ah[r0 * AST + aw + 4], ah3 = s.Ah[(r0 + 8) * AST + aw + 4];
                u32 al0 = s.Al[r0 * AST + aw],     al1 = s.Al[(r0 + 8) * AST + aw];
                u32 al2 = s.Al[r0 * AST + aw + 4], al3 = s.Al[(r0 + 8) * AST + aw + 4];
#pragma unroll
                for (int nt = 0; nt < 8; nt++) {
                    int n = hhalf * 64 + nt * 8 + (lane >> 2);
                    u32 bh0 = s.W3h[n * AST + aw], bh1 = s.W3h[n * AST + aw + 4];
                    u32 bl0 = s.W3l[n * AST + aw], bl1 = s.W3l[n * AST + aw + 4];
                    mma16816(acc[nt], ah0, ah1, ah2, ah3, bh0, bh1);
                    mma16816(acc[nt], ah0, ah1, ah2, ah3, bl0, bl1);
                    mma16816(acc[nt], al0, al1, al2, al3, bh0, bh1);
                }
            }
#pragma unroll
            for (int nt = 0; nt < 8; nt++) {
                float m0 = fmaxf(va ? acc[nt][0] : -1e30f, vb ? acc[nt][2] : -1e30f);
                float m1 = fmaxf(va ? acc[nt][1] : -1e30f, vb ? acc[nt][3] : -1e30f);
#pragma unroll
                for (int off = 16; off >= 4; off >>= 1) {
                    m0 = fmaxf(m0, __shfl_down_sync(0xffffffffu, m0, off));
                    m1 = fmaxf(m1, __shfl_down_sync(0xffffffffu, m1, off));
                }
                if (lane < 4) {
                    int cn = hhalf * 64 + nt * 8 + lane * 2;
                    s.pool[wid][cn]     = m0;
                    s.pool[wid][cn + 1] = m1;
                }
            }
        }
    }
    __syncthreads();

    // ---- combine 4 warps per center + bias ----
    {
        int center = tid >> 7, ch = tid & 127;
        int w0 = center * 4;
        float v = s.pool[w0][ch];
        v = fmaxf(v, s.pool[w0 + 1][ch]);
        v = fmaxf(v, s.pool[w0 + 2][ch]);
        v = fmaxf(v, s.pool[w0 + 3][ch]);
        out[(size_t)(c0 + center) * OUTD + ch] = v + s.b3s[ch];
    }
}

// =========================================================================
extern "C" void kernel_launch(void* const* d_in, const int* in_sizes, int n_in,
                              void* d_out, int out_size)
{
    const float* x   = (const float*)d_in[0];
    const float* pos = (const float*)d_in[1];
    const float* W1  = (const float*)d_in[2];
    const float* b1  = (const float*)d_in[3];
    const float* W2  = (const float*)d_in[4];
    const float* b2  = (const float*)d_in[5];
    const float* W3  = (const float*)d_in[6];
    const float* b3  = (const float*)d_in[7];

    float* out       = (float*)d_out;
    float* pos_s_out = out + (size_t)BATCH * MCTR * OUTD;

    cudaFuncSetAttribute(fpsfeat_kernel,
                         cudaFuncAttributeMaxDynamicSharedMemorySize, (int)sizeof(MSmem));
    cudaFuncSetAttribute(center_kernel,
                         cudaFuncAttributeMaxDynamicSharedMemorySize, (int)sizeof(CKS));

    fpsfeat_kernel<<<PREP_BLOCK + 1, 256, sizeof(MSmem)>>>(
        pos, pos_s_out, x, W1, W2, W3);
    center_kernel<<<BATCH * MCTR / 2, 256, sizeof(CKS)>>>(
        pos, W1, b1, b2, b3, out);
}

// round 11
// speedup vs baseline: 2.0585x; 1.3283x over previous
#include <cuda_runtime.h>
#include <cuda_bf16.h>
#include <cstdint>

#define NPTS 4096
#define BATCH 16
#define MCTR 1024
#define KNBR 64
#define OUTD 128
#define R2C  0.04f
#define CANDC 512

#define FPS_BLOCKS 16
#define FEAT_ROWS 64
#define FEAT_BLOCKS ((BATCH * NPTS) / FEAT_ROWS)     // 1024 (64 per batch)
#define PREP_ID   (FPS_BLOCKS + FEAT_BLOCKS)         // 1040
#define CENTER0   (PREP_ID + 1)                      // 1041
#define NCBLK     (BATCH * MCTR / 2)                 // 8192
#define GRID_ALL  (CENTER0 + NCBLK)                  // 9233

#define AST 36   // padded u32 stride for bf16-pair tiles (conflict-free frags)

typedef unsigned long long ull;
typedef unsigned int u32;
typedef unsigned short u16;

// ---------------- device scratch ----------------
__device__ int   g_idx[BATCH * MCTR];
__device__ float g_feat[(size_t)BATCH * NPTS * 64];   // x @ W1[0:64,:]
__device__ u32   g_W2h[64 * 32],  g_W2l[64 * 32];     // W2^T bf16-pairs [n][k/2]
__device__ u32   g_W3h[128 * 32], g_W3l[128 * 32];    // W3^T bf16-pairs
// sync flags: [0..15] fps progress per batch, [16..31] feat done count per batch,
// [32] prep done. Reset to 0 by cudaMemsetAsync before each launch.
__device__ int   g_sync[48];

// ---------------- acquire/release helpers ----------------
__device__ __forceinline__ int ld_acq(const int* p) {
    int v; asm volatile("ld.acquire.gpu.global.s32 %0, [%1];" : "=r"(v) : "l"(p)); return v;
}
__device__ __forceinline__ void st_rel(int* p, int v) {
    asm volatile("st.release.gpu.global.s32 [%0], %1;" :: "l"(p), "r"(v) : "memory");
}

// ---------------- f32x2 helpers ----------------
__device__ __forceinline__ ull fma2(ull a, ull b, ull c) {
    ull d; asm("fma.rn.f32x2 %0, %1, %2, %3;" : "=l"(d) : "l"(a), "l"(b), "l"(c));
    return d;
}
__device__ __forceinline__ ull pack2(float lo, float hi) {
    ull d; asm("mov.b64 %0, {%1, %2};" : "=l"(d) : "f"(lo), "f"(hi)); return d;
}
__device__ __forceinline__ float2 unpack2(ull v) {
    float2 r; asm("mov.b64 {%0, %1}, %2;" : "=f"(r.x), "=f"(r.y) : "l"(v)); return r;
}

// ---------------- mma.sync m16n8k16 bf16 ----------------
__device__ __forceinline__ void mma16816(float* c, u32 a0, u32 a1, u32 a2, u32 a3,
                                         u32 b0, u32 b1) {
    asm volatile(
        "mma.sync.aligned.m16n8k16.row.col.f32.bf16.bf16.f32 "
        "{%0,%1,%2,%3}, {%4,%5,%6,%7}, {%8,%9}, {%0,%1,%2,%3};"
        : "+f"(c[0]), "+f"(c[1]), "+f"(c[2]), "+f"(c[3])
        : "r"(a0), "r"(a1), "r"(a2), "r"(a3), "r"(b0), "r"(b1));
}

__device__ __forceinline__ void split_bf16(float v, u16& hi, u16& lo) {
    __nv_bfloat16 bh = __float2bfloat16(v);
    float r = v - __bfloat162float(bh);
    __nv_bfloat16 bl = __float2bfloat16(r);
    hi = __bfloat16_as_ushort(bh);
    lo = __bfloat16_as_ushort(bl);
}
__device__ __forceinline__ u32 split_pack_hi(float v0, float v1) {
    u16 h0, l0, h1, l1;
    split_bf16(v0, h0, l0); split_bf16(v1, h1, l1);
    return (u32)h0 | ((u32)h1 << 16);
}
__device__ __forceinline__ u32 split_pack_lo(float v0, float v1) {
    u16 h0, l0, h1, l1;
    split_bf16(v0, h0, l0); split_bf16(v1, h1, l1);
    return (u32)l0 | ((u32)l1 << 16);
}

// ---------------- shared-memory layouts ----------------
struct CKS {                       // center path (~106 KB)
    ull   keys[2 * CANDC];
    u32   Ah[128 * AST];
    u32   Al[128 * AST];
    u32   W2h[64 * AST];
    u32   W2l[64 * AST];
    u32   W3h[128 * AST];
    u32   W3l[128 * AST];
    float pool[8][132];
    float b1s[64], b2s[64], b3s[128];
    float w1b[3 * 64];
    float rel[128 * 3];
    int   nbr[128];
    float ctr[6];
    int   cnt[2], nvv[2];
};

struct alignas(16) FSmem {
    union {
        struct {
            float px[NPTS], py[NPTS], pz[NPTS];
            ull   part[2][8];
        } fps;
        struct {
            float xx[FEAT_ROWS][65];
            float w[64][64];
        } feat;
        CKS center;
    } u;
};

// =========================================================================
// One fused kernel. Producers (low block ids, never wait) feed consumers
// (center blocks, interleaved m-major across batches) via g_sync flags.
// =========================================================================
__global__ __launch_bounds__(256, 2) void fused_kernel(
    const float* __restrict__ pos, float* __restrict__ pos_s_out,
    const float* __restrict__ x,   const float* __restrict__ W1,
    const float* __restrict__ W2,  const float* __restrict__ W3,
    const float* __restrict__ b1,  const float* __restrict__ b2,
    const float* __restrict__ b3,  float* __restrict__ out)
{
    extern __shared__ unsigned char smraw[];
    FSmem& sm = *reinterpret_cast<FSmem*>(smraw);
    int tid = threadIdx.x;

    if (blockIdx.x < FPS_BLOCKS) {
        // ========================= FPS (producer) =========================
        auto& S = sm.u.fps;
        int b = blockIdx.x;
        const float* pb = pos + (size_t)b * NPTS * 3;

        float px[16], py[16], pz[16], dst[16];
#pragma unroll
        for (int u = 0; u < 16; u++) {
            int i = tid + u * 256;
            float X = pb[i * 3 + 0], Y = pb[i * 3 + 1], Z = pb[i * 3 + 2];
            S.px[i] = X; S.py[i] = Y; S.pz[i] = Z;
            px[u] = X; py[u] = Y; pz[u] = Z;
            dst[u] = 1e10f;
        }
        __syncthreads();

        int   last = 0;
        float lx = S.px[0], ly = S.py[0], lz = S.pz[0];

        for (int m = 0; m < MCTR; m++) {
            if (tid == 0) {
                g_idx[b * MCTR + m] = last;
                float* po = pos_s_out + ((size_t)(b * MCTR + m)) * 3;
                po[0] = lx; po[1] = ly; po[2] = lz;
                st_rel(&g_sync[b], m + 1);      // publish progress (release)
            }
            float bv = -1.0f; int bi = 0;
#pragma unroll
            for (int u = 0; u < 16; u++) {
                float dx = px[u] - lx, dy = py[u] - ly, dz = pz[u] - lz;
                float d  = fmaf(dx, dx, fmaf(dy, dy, dz * dz));
                float nd = fminf(dst[u], d);
                dst[u] = nd;
                int gi = tid + u * 256;
                if (nd > bv) { bv = nd; bi = gi; }
            }
            unsigned bvb  = __float_as_uint(bv);
            unsigned wmax = __reduce_max_sync(0xffffffffu, bvb);
            unsigned cand = (bvb == wmax) ? (unsigned)bi : 0xffffffffu;
            unsigned wbi  = __reduce_min_sync(0xffffffffu, cand);
            ull key = ((ull)wmax << 32) | (unsigned)(~wbi);
            if ((tid & 31) == 0) S.part[m & 1][tid >> 5] = key;
            __syncthreads();
            ull best = S.part[m & 1][0];
#pragma unroll
            for (int w = 1; w < 8; w++) {
                ull k2 = S.part[m & 1][w];
                if (k2 > best) best = k2;
            }
            last = (int)(~(unsigned)best);
            lx = S.px[last]; ly = S.py[last]; lz = S.pz[last];
        }
    } else if (blockIdx.x < PREP_ID) {
        // ========================= feat (producer) ========================
        auto& S = sm.u.feat;
        int fblk = blockIdx.x - FPS_BLOCKS;
        size_t rbase = (size_t)fblk * FEAT_ROWS;

        for (int i = tid; i < 64 * 64; i += 256) S.w[i >> 6][i & 63] = W1[i];
        for (int i = tid; i < FEAT_ROWS * 64; i += 256)
            S.xx[i >> 6][i & 63] = x[rbase * 64 + i];
        __syncthreads();

        int r = tid >> 2, q = tid & 3;
        ull acc[8];
#pragma unroll
        for (int c = 0; c < 8; c++) acc[c] = 0ull;
        for (int k = 0; k < 64; k++) {
            float xv = S.xx[r][k];
            ull xb = pack2(xv, xv);
            const ulonglong2* wp = reinterpret_cast<const ulonglong2*>(&S.w[k][q * 16]);
            ulonglong2 w0 = wp[0], w1 = wp[1], w2 = wp[2], w3 = wp[3];
            acc[0] = fma2(xb, w0.x, acc[0]); acc[1] = fma2(xb, w0.y, acc[1]);
            acc[2] = fma2(xb, w1.x, acc[2]); acc[3] = fma2(xb, w1.y, acc[3]);
            acc[4] = fma2(xb, w2.x, acc[4]); acc[5] = fma2(xb, w2.y, acc[5]);
            acc[6] = fma2(xb, w3.x, acc[6]); acc[7] = fma2(xb, w3.y, acc[7]);
        }
        float* go = g_feat + (rbase + r) * 64 + q * 16;
#pragma unroll
        for (int c = 0; c < 4; c++) {
            float2 a = unpack2(acc[c * 2]), bq = unpack2(acc[c * 2 + 1]);
            *reinterpret_cast<float4*>(go + c * 4) = make_float4(a.x, a.y, bq.x, bq.y);
        }
        __threadfence();
        __syncthreads();
        if (tid == 0) atomicAdd(&g_sync[16 + (fblk >> 6)], 1);   // 64 blocks/batch
    } else if (blockIdx.x == PREP_ID) {
        // ==================== weight split prep (producer) ================
        for (int i = tid; i < 64 * 64; i += 256) {     // W2: n=i>>6, k=i&63
            int nn = i >> 6, k = i & 63;
            u16 hi, lo;
            split_bf16(W2[k * 64 + nn], hi, lo);
            int w = nn * 32 + (k >> 1);
            ((u16*)g_W2h)[w * 2 + (k & 1)] = hi;
            ((u16*)g_W2l)[w * 2 + (k & 1)] = lo;
        }
        for (int i = tid; i < 128 * 64; i += 256) {    // W3
            int nn = i >> 6, k = i & 63;
            u16 hi, lo;
            split_bf16(W3[k * 128 + nn], hi, lo);
            int w = nn * 32 + (k >> 1);
            ((u16*)g_W3h)[w * 2 + (k & 1)] = hi;
            ((u16*)g_W3l)[w * 2 + (k & 1)] = lo;
        }
        __threadfence();
        __syncthreads();
        if (tid == 0) atomicAdd(&g_sync[32], 1);
    } else {
        // ========================= center (consumer) ======================
        CKS& s = sm.u.center;
        int wid = tid >> 5, lane = tid & 31;
        int cblk = blockIdx.x - CENTER0;
        int b  = cblk & 15;            // m-major interleave across batches
        int m2 = cblk >> 4;            // center pair 0..511
        int c0 = b * MCTR + m2 * 2;
        const float* pb = pos + (size_t)b * NPTS * 3;

        // ---- spin until producers ready (thread 0 only) ----
        if (tid == 0) {
            while (ld_acq(&g_sync[32]) < 1)        __nanosleep(128);
            while (ld_acq(&g_sync[16 + b]) < 64)   __nanosleep(128);
            int need = (m2 * 2 & 1023) + 2;
            while (ld_acq(&g_sync[b]) < need)      __nanosleep(128);
            __threadfence();
        }
        __syncthreads();

        if (tid == 0) {
            s.cnt[0] = 0; s.cnt[1] = 0;
            int ci0 = g_idx[c0], ci1 = g_idx[c0 + 1];
            s.ctr[0] = pb[ci0 * 3 + 0]; s.ctr[1] = pb[ci0 * 3 + 1]; s.ctr[2] = pb[ci0 * 3 + 2];
            s.ctr[3] = pb[ci1 * 3 + 0]; s.ctr[4] = pb[ci1 * 3 + 1]; s.ctr[5] = pb[ci1 * 3 + 2];
        }
        if (tid < 128) {
            s.nbr[tid] = 0;
            s.rel[tid * 3 + 0] = 0.f; s.rel[tid * 3 + 1] = 0.f; s.rel[tid * 3 + 2] = 0.f;
        }

        // ---- weight copy (pre-split u32s, L2-resident) ----
        for (int i = tid; i < 64 * 32; i += 256) {
            int nn = i >> 5, kk = i & 31;
            s.W2h[nn * AST + kk] = g_W2h[i];
            s.W2l[nn * AST + kk] = g_W2l[i];
        }
        for (int i = tid; i < 128 * 32; i += 256) {
            int nn = i >> 5, kk = i & 31;
            s.W3h[nn * AST + kk] = g_W3h[i];
            s.W3l[nn * AST + kk] = g_W3l[i];
        }
        if (tid < 192) s.w1b[tid] = W1[64 * 64 + tid];
        if (tid < 64)       { s.b1s[tid] = b1[tid]; s.b2s[tid] = b2[tid]; }
        else if (tid < 192) s.b3s[tid - 64] = b3[tid - 64];
        __syncthreads();
        float cx0 = s.ctr[0], cy0 = s.ctr[1], cz0 = s.ctr[2];
        float cx1 = s.ctr[3], cy1 = s.ctr[4], cz1 = s.ctr[5];

        // ---- phase 1: shared candidate scan ----
        for (int i = tid; i < NPTS; i += 256) {
            float X = pb[i * 3 + 0], Y = pb[i * 3 + 1], Z = pb[i * 3 + 2];
            float dx0 = X - cx0, dy0 = Y - cy0, dz0 = Z - cz0;
            float d20 = fmaf(dx0, dx0, fmaf(dy0, dy0, dz0 * dz0));
            if (d20 <= R2C) {
                int p = atomicAdd(&s.cnt[0], 1);
                if (p < CANDC) s.keys[p] = ((ull)__float_as_uint(d20) << 32) | (unsigned)i;
            }
            float dx1 = X - cx1, dy1 = Y - cy1, dz1 = Z - cz1;
            float d21 = fmaf(dx1, dx1, fmaf(dy1, dy1, dz1 * dz1));
            if (d21 <= R2C) {
                int p = atomicAdd(&s.cnt[1], 1);
                if (p < CANDC) s.keys[CANDC + p] = ((ull)__float_as_uint(d21) << 32) | (unsigned)i;
            }
        }
        __syncthreads();

        // ---- phase 2: rank-count selection ----
        for (int cc = 0; cc < 2; cc++) {
            int n  = min(s.cnt[cc], CANDC);
            int nv = min(n, KNBR);
            const ull* kk = s.keys + cc * CANDC;
            float ccx = cc ? cx1 : cx0, ccy = cc ? cy1 : cy0, ccz = cc ? cz1 : cz0;
            ull myk[2]; int rnk[2];
#pragma unroll
            for (int t = 0; t < 2; t++) {
                int i = tid + t * 256;
                myk[t] = (i < n) ? kk[i] : ~0ull;
                rnk[t] = 0;
            }
            for (int j = 0; j < n; j++) {
                ull kj = kk[j];
#pragma unroll
                for (int t = 0; t < 2; t++) rnk[t] += (kj < myk[t]) ? 1 : 0;
            }
#pragma unroll
            for (int t = 0; t < 2; t++) {
                int i = tid + t * 256;
                if (i < n && rnk[t] < KNBR) {
                    int idx = (int)(myk[t] & 0xffffffffu);
                    int slot = cc * 64 + rnk[t];
                    s.nbr[slot] = idx;
                    s.rel[slot * 3 + 0] = pb[idx * 3 + 0] - ccx;
                    s.rel[slot * 3 + 1] = pb[idx * 3 + 1] - ccy;
                    s.rel[slot * 3 + 2] = pb[idx * 3 + 2] - ccz;
                }
            }
            if (tid == 0) s.nvv[cc] = nv;
        }
        __syncthreads();

        int nv0 = s.nvv[0], nv1 = s.nvv[1];

        // ---- h1 (scalar fp32) -> split bf16 A tile ----
        {
            int row = tid >> 1, half = tid & 1;
            int j = s.nbr[row];
            const float4* gr = reinterpret_cast<const float4*>(
                g_feat + ((size_t)(b * NPTS + j)) * 64 + half * 32);
            float rx = s.rel[row * 3 + 0], ry = s.rel[row * 3 + 1], rz = s.rel[row * 3 + 2];
#pragma unroll
            for (int c4 = 0; c4 < 8; c4++) {
                float4 g = gr[c4];
                float v[4] = {g.x, g.y, g.z, g.w};
                float o[4];
#pragma unroll
                for (int c = 0; c < 4; c++) {
                    int ch = half * 32 + c4 * 4 + c;
                    float t = v[c];
                    t = fmaf(rx, s.w1b[ch], t);
                    t = fmaf(ry, s.w1b[64 + ch], t);
                    t = fmaf(rz, s.w1b[128 + ch], t);
                    o[c] = fmaxf(t + s.b1s[ch], 0.f);
                }
                int w = row * AST + half * 16 + c4 * 2;
                s.Ah[w]     = split_pack_hi(o[0], o[1]);
                s.Al[w]     = split_pack_lo(o[0], o[1]);
                s.Ah[w + 1] = split_pack_hi(o[2], o[3]);
                s.Al[w + 1] = split_pack_lo(o[2], o[3]);
            }
        }
        __syncthreads();

        int r0 = wid * 16 + (lane >> 2);
        int lp = lane & 3;

        // ================= layer 2: h2[128,64] = A @ W2^T =================
        {
            float acc[8][4];
#pragma unroll
            for (int nt = 0; nt < 8; nt++)
#pragma unroll
                for (int c = 0; c < 4; c++) acc[nt][c] = 0.f;

#pragma unroll
            for (int kt = 0; kt < 4; kt++) {
                int aw = kt * 8 + lp;
                u32 ah0 = s.Ah[r0 * AST + aw],       ah1 = s.Ah[(r0 + 8) * AST + aw];
                u32 ah2 = s.Ah[r0 * AST + aw + 4],   ah3 = s.Ah[(r0 + 8) * AST + aw + 4];
                u32 al0 = s.Al[r0 * AST + aw],       al1 = s.Al[(r0 + 8) * AST + aw];
                u32 al2 = s.Al[r0 * AST + aw + 4],   al3 = s.Al[(r0 + 8) * AST + aw + 4];
#pragma unroll
                for (int nt = 0; nt < 8; nt++) {
                    int n = nt * 8 + (lane >> 2);
                    u32 bh0 = s.W2h[n * AST + aw], bh1 = s.W2h[n * AST + aw + 4];
                    u32 bl0 = s.W2l[n * AST + aw], bl1 = s.W2l[n * AST + aw + 4];
                    mma16816(acc[nt], ah0, ah1, ah2, ah3, bh0, bh1);
                    mma16816(acc[nt], ah0, ah1, ah2, ah3, bl0, bl1);
                    mma16816(acc[nt], al0, al1, al2, al3, bh0, bh1);
                }
            }
#pragma unroll
            for (int nt = 0; nt < 8; nt++) {
                int cn = nt * 8 + lp * 2;
                float bb0 = s.b2s[cn], bb1 = s.b2s[cn + 1];
                float v0 = fmaxf(acc[nt][0] + bb0, 0.f);
                float v1 = fmaxf(acc[nt][1] + bb1, 0.f);
                float v2 = fmaxf(acc[nt][2] + bb0, 0.f);
                float v3 = fmaxf(acc[nt][3] + bb1, 0.f);
                int w = nt * 4 + lp;
                s.Ah[r0 * AST + w]       = split_pack_hi(v0, v1);
                s.Al[r0 * AST + w]       = split_pack_lo(v0, v1);
                s.Ah[(r0 + 8) * AST + w] = split_pack_hi(v2, v3);
                s.Al[(r0 + 8) * AST + w] = split_pack_lo(v2, v3);
            }
        }
        __syncwarp();

        // ================= layer 3: out[128,128] = A @ W3^T + masked max ====
        {
            int rin = (wid & 3) * 16 + (lane >> 2);
            int nv  = (wid >> 2) ? nv1 : nv0;
            bool va = rin < nv, vb = (rin + 8) < nv;

            for (int hhalf = 0; hhalf < 2; hhalf++) {
                float acc[8][4];
#pragma unroll
                for (int nt = 0; nt < 8; nt++)
#pragma unroll
                    for (int c = 0; c < 4; c++) acc[nt][c] = 0.f;

#pragma unroll
                for (int kt = 0; kt < 4; kt++) {
                    int aw = kt * 8 + lp;
                    u32 ah0 = s.Ah[r0 * AST + aw],     ah1 = s.Ah[(r0 + 8) * AST + aw];
                    u32 ah2 = s.Ah[r0 * AST + aw + 4], ah3 = s.Ah[(r0 + 8) * AST + aw + 4];
                    u32 al0 = s.Al[r0 * AST + aw],     al1 = s.Al[(r0 + 8) * AST + aw];
                    u32 al2 = s.Al[r0 * AST + aw + 4], al3 = s.Al[(r0 + 8) * AST + aw + 4];
#pragma unroll
                    for (int nt = 0; nt < 8; nt++) {
                        int n = hhalf * 64 + nt * 8 + (lane >> 2);
                        u32 bh0 = s.W3h[n * AST + aw], bh1 = s.W3h[n * AST + aw + 4];
                        u32 bl0 = s.W3l[n * AST + aw], bl1 = s.W3l[n * AST + aw + 4];
                        mma16816(acc[nt], ah0, ah1, ah2, ah3, bh0, bh1);
                        mma16816(acc[nt], ah0, ah1, ah2, ah3, bl0, bl1);
                        mma16816(acc[nt], al0, al1, al2, al3, bh0, bh1);
                    }
                }
#pragma unroll
                for (int nt = 0; nt < 8; nt++) {
                    float m0 = fmaxf(va ? acc[nt][0] : -1e30f, vb ? acc[nt][2] : -1e30f);
                    float m1 = fmaxf(va ? acc[nt][1] : -1e30f, vb ? acc[nt][3] : -1e30f);
#pragma unroll
                    for (int off = 16; off >= 4; off >>= 1) {
                        m0 = fmaxf(m0, __shfl_down_sync(0xffffffffu, m0, off));
                        m1 = fmaxf(m1, __shfl_down_sync(0xffffffffu, m1, off));
                    }
                    if (lane < 4) {
                        int cn = hhalf * 64 + nt * 8 + lane * 2;
                        s.pool[wid][cn]     = m0;
                        s.pool[wid][cn + 1] = m1;
                    }
                }
            }
        }
        __syncthreads();

        // ---- combine 4 warps per center + bias ----
        {
            int center = tid >> 7, ch = tid & 127;
            int w0 = center * 4;
            float v = s.pool[w0][ch];
            v = fmaxf(v, s.pool[w0 + 1][ch]);
            v = fmaxf(v, s.pool[w0 + 2][ch]);
            v = fmaxf(v, s.pool[w0 + 3][ch]);
            out[(size_t)(c0 + center) * OUTD + ch] = v + s.b3s[ch];
        }
    }
}

// =========================================================================
extern "C" void kernel_launch(void* const* d_in, const int* in_sizes, int n_in,
                              void* d_out, int out_size)
{
    const float* x   = (const float*)d_in[0];
    const float* pos = (const float*)d_in[1];
    const float* W1  = (const float*)d_in[2];
    const float* b1  = (const float*)d_in[3];
    const float* W2  = (const float*)d_in[4];
    const float* b2  = (const float*)d_in[5];
    const float* W3  = (const float*)d_in[6];
    const float* b3  = (const float*)d_in[7];

    float* out       = (float*)d_out;
    float* pos_s_out = out + (size_t)BATCH * MCTR * OUTD;

    cudaFuncSetAttribute(fused_kernel,
                         cudaFuncAttributeMaxDynamicSharedMemorySize, (int)sizeof(FSmem));

    // reset sync flags (graph-capturable async memset; no allocation)
    void* sp = nullptr;
    cudaGetSymbolAddress(&sp, g_sync);
    cudaMemsetAsync(sp, 0, 48 * sizeof(int), 0);

    fused_kernel<<<GRID_ALL, 256, sizeof(FSmem)>>>(
        pos, pos_s_out, x, W1, W2, W3, b1, b2, b3, out);
}